// round 5
// baseline (speedup 1.0000x reference)
#include <cuda_runtime.h>
#include <math.h>

#define NN     50000
#define NEDGE  600000
#define HDIM   128
#define NPASS  5
#define LN_EPS 1e-6f

#define NODE_TILES ((NN + 63) / 64)   // 782
#define EDGE_TILES (NEDGE / 64)       // 9375 (exact)

typedef unsigned long long ull;

// Persistent device scratch
__device__ float g_n[NN * HDIM];        // node features
__device__ float g_S[NN * HDIM];        // per-pass scatter of n[sender]
__device__ float g_hsum[NN * HDIM];     // sum of edge hidden h over receivers
__device__ float g_deg[NN];             // in-degree (float)
__device__ float g_cagg[NN * HDIM];     // loop-invariant agg contribution @ W0_bot
__device__ float g_T1[HDIM * HDIM];     // W1e @ Wm_bot
__device__ float g_tvec[HDIM];          // b1e @ Wm_bot
__device__ float g_Wg[HDIM * HDIM];     // W1e @ Wm_bot @ W0_bot
__device__ float g_bg[HDIM];            // b1e @ Wm_bot @ W0_bot
__device__ float g_Wf[HDIM * HDIM];     // Wm_top @ W0_bot

// ---------------------------------------------------------------------------
// f32x2 packed helpers
// ---------------------------------------------------------------------------
__device__ __forceinline__ ull pk2(float x, float y) {
    ull r; asm("mov.b64 %0, {%1, %2};" : "=l"(r) : "f"(x), "f"(y)); return r;
}
__device__ __forceinline__ float2 upk2(ull v) {
    float2 f; asm("mov.b64 {%0, %1}, %2;" : "=f"(f.x), "=f"(f.y) : "l"(v)); return f;
}
__device__ __forceinline__ ull add2(ull a, ull b) {
    ull r; asm("add.rn.f32x2 %0, %1, %2;" : "=l"(r) : "l"(a), "l"(b)); return r;
}
#define FMA2(acc, a, b) asm("fma.rn.f32x2 %0, %1, %2, %0;" : "+l"(acc) : "l"(a), "l"(b))

#define LDT 68   // A_T row pad: 68*4=272 B -> 16B-aligned rows, 4-way store conflict max

// ---------------------------------------------------------------------------
// Row-paired packed GEMM micro-step.  Block 256 thr, tile 64 x 128.
// A_T: transposed A in smem [KC][LDT] floats; rows adjacent ->
// one ulonglong2 load = packed operands for 4 rows (2 pairs), broadcast.
// acc[p][c]: rows (m0+2p, m0+2p+1), col j+c.
// ---------------------------------------------------------------------------
template<int KC>
__device__ __forceinline__ void gemm2r_step(const float* __restrict__ A_T,
                                            const float* __restrict__ B_s,
                                            int m0, int j, ull acc[4][4]) {
#pragma unroll
    for (int kk = 0; kk < KC; kk++) {
        float4 b = *(const float4*)(B_s + kk * HDIM + j);
        ull b0 = pk2(b.x, b.x), b1 = pk2(b.y, b.y);
        ull b2 = pk2(b.z, b.z), b3 = pk2(b.w, b.w);
        ulonglong2 a01 = *(const ulonglong2*)(A_T + kk * LDT + m0);
        ulonglong2 a23 = *(const ulonglong2*)(A_T + kk * LDT + m0 + 4);
        FMA2(acc[0][0], a01.x, b0); FMA2(acc[0][1], a01.x, b1);
        FMA2(acc[0][2], a01.x, b2); FMA2(acc[0][3], a01.x, b3);
        FMA2(acc[1][0], a01.y, b0); FMA2(acc[1][1], a01.y, b1);
        FMA2(acc[1][2], a01.y, b2); FMA2(acc[1][3], a01.y, b3);
        FMA2(acc[2][0], a23.x, b0); FMA2(acc[2][1], a23.x, b1);
        FMA2(acc[2][2], a23.x, b2); FMA2(acc[2][3], a23.x, b3);
        FMA2(acc[3][0], a23.y, b0); FMA2(acc[3][1], a23.y, b1);
        FMA2(acc[3][2], a23.y, b2); FMA2(acc[3][3], a23.y, b3);
    }
}

// ---------------------------------------------------------------------------
// Weight folds
// ---------------------------------------------------------------------------
__global__ void k_fold1(const float* __restrict__ W1e, const float* __restrict__ b1e,
                        const float* __restrict__ Wm) {
    __shared__ float a[HDIM];
    int j = threadIdx.x;
    a[j] = (blockIdx.x < 128) ? W1e[blockIdx.x * HDIM + j] : b1e[j];
    __syncthreads();
    float s = 0.f;
#pragma unroll 8
    for (int l = 0; l < HDIM; l++)
        s = fmaf(a[l], Wm[(HDIM + l) * HDIM + j], s);
    if (blockIdx.x < 128) g_T1[blockIdx.x * HDIM + j] = s;
    else                  g_tvec[j] = s;
}

__global__ void k_fold2(const float* __restrict__ W0n, const float* __restrict__ Wm) {
    __shared__ float a[HDIM];
    int j = threadIdx.x;
    int bid = blockIdx.x;
    if (bid < 128)       a[j] = g_T1[bid * HDIM + j];
    else if (bid == 128) a[j] = g_tvec[j];
    else                 a[j] = Wm[(bid - 129) * HDIM + j];   // Wm_top rows
    __syncthreads();
    float s = 0.f;
#pragma unroll 8
    for (int l = 0; l < HDIM; l++)
        s = fmaf(a[l], W0n[(HDIM + l) * HDIM + j], s);        // W0_bot
    if (bid < 128)       g_Wg[bid * HDIM + j] = s;
    else if (bid == 128) g_bg[j] = s;
    else                 g_Wf[(bid - 129) * HDIM + j] = s;
}

// ---------------------------------------------------------------------------
// Zero helpers
// ---------------------------------------------------------------------------
__global__ void k_zero_pre() {   // zero g_hsum and g_deg
    int i = blockIdx.x * blockDim.x + threadIdx.x;
    if (i < NN * 32) ((float4*)g_hsum)[i] = make_float4(0.f, 0.f, 0.f, 0.f);
    else {
        int d = i - NN * 32;
        if (d < NN / 4) ((float4*)g_deg)[d] = make_float4(0.f, 0.f, 0.f, 0.f);
    }
}
__global__ void k_zero_S() {
    int i = blockIdx.x * blockDim.x + threadIdx.x;
    if (i < NN * 32) ((float4*)g_S)[i] = make_float4(0.f, 0.f, 0.f, 0.f);
}

// Shared-memory layout (bytes) for the big kernels:
//   A_T : [32][68] float -> 8704
//   h_s : [64][132] float-> 33792
//   B_s : [32][128] float-> 16384
//   B2_s: [32][128] float-> 16384 (node_upd only)
#define OFF_AT  0
#define OFF_H   (32 * LDT * 4)
#define OFF_B   (OFF_H + 64 * 132 * 4)
#define OFF_B2  (OFF_B + 32 * 128 * 4)
#define SM_ENC  OFF_B2                     // 58880
#define SM_UPD  (OFF_B2 + 32 * 128 * 4)    // 75264

// Fill A_T[kk][m] (kk 0..31) from row-major src with row stride RS, col offset koff.
template<int RS>
__device__ __forceinline__ void fill_AT32(float* A_T, const float* __restrict__ src,
                                          int row0, int koff, int tid) {
#pragma unroll
    for (int i = 0; i < 8; i++) {
        int idx = tid + i * 256;
        int m = idx >> 5, kk = idx & 31;
        int gr = row0 + m;
        float v = (gr < NN) ? src[(long)gr * RS + koff + kk] : 0.f;
        A_T[kk * LDT + m] = v;
    }
}
// Same but from smem h_s ([64][132] row-major), chunk c
__device__ __forceinline__ void fill_AT32_h(float* A_T, const float* h_s,
                                            int c, int tid) {
#pragma unroll
    for (int i = 0; i < 8; i++) {
        int idx = tid + i * 256;
        int m = idx >> 5, kk = idx & 31;
        A_T[kk * LDT + m] = h_s[m * 132 + c * 32 + kk];
    }
}

// ---------------------------------------------------------------------------
// Node encoder: n = relu(x@W0+b0)@W1+b1
// ---------------------------------------------------------------------------
__global__ void k_node_enc(const float* __restrict__ x,
                           const float* __restrict__ W0, const float* __restrict__ b0,
                           const float* __restrict__ W1, const float* __restrict__ b1) {
    extern __shared__ char smraw[];
    float* A_T = (float*)(smraw + OFF_AT);
    float* h_s = (float*)(smraw + OFF_H);
    float* B_s = (float*)(smraw + OFF_B);

    const int tid = threadIdx.x;
    const int ty = tid >> 5, tx = tid & 31;
    const int m0 = ty * 8;
    const int j  = tx * 4;
    const int row0 = blockIdx.x * 64;

    // layer 1: K = 32
    fill_AT32<32>(A_T, x, row0, 0, tid);
#pragma unroll
    for (int i = 0; i < 16; i++) B_s[tid + i * 256] = W0[tid + i * 256];
    __syncthreads();

    ull acc[4][4];
    {
        float4 bv = *(const float4*)(b0 + j);
#pragma unroll
        for (int p = 0; p < 4; p++) {
            acc[p][0] = pk2(bv.x, bv.x); acc[p][1] = pk2(bv.y, bv.y);
            acc[p][2] = pk2(bv.z, bv.z); acc[p][3] = pk2(bv.w, bv.w);
        }
    }
    gemm2r_step<32>(A_T, B_s, m0, j, acc);
    __syncthreads();

#pragma unroll
    for (int p = 0; p < 4; p++) {
        float2 a0 = upk2(acc[p][0]), a1 = upk2(acc[p][1]);
        float2 a2 = upk2(acc[p][2]), a3 = upk2(acc[p][3]);
        *(float4*)(h_s + (m0 + 2*p    ) * 132 + j) =
            make_float4(fmaxf(a0.x,0.f), fmaxf(a1.x,0.f), fmaxf(a2.x,0.f), fmaxf(a3.x,0.f));
        *(float4*)(h_s + (m0 + 2*p + 1) * 132 + j) =
            make_float4(fmaxf(a0.y,0.f), fmaxf(a1.y,0.f), fmaxf(a2.y,0.f), fmaxf(a3.y,0.f));
    }

    // layer 2: K = 128 in 4 chunks
    ull o[4][4];
    {
        float4 bv = *(const float4*)(b1 + j);
#pragma unroll
        for (int p = 0; p < 4; p++) {
            o[p][0] = pk2(bv.x, bv.x); o[p][1] = pk2(bv.y, bv.y);
            o[p][2] = pk2(bv.z, bv.z); o[p][3] = pk2(bv.w, bv.w);
        }
    }
    for (int c = 0; c < 4; c++) {
        __syncthreads();
        fill_AT32_h(A_T, h_s, c, tid);
#pragma unroll
        for (int i = 0; i < 16; i++) B_s[tid + i * 256] = W1[c * 32 * 128 + tid + i * 256];
        __syncthreads();
        gemm2r_step<32>(A_T, B_s, m0, j, o);
    }
#pragma unroll
    for (int p = 0; p < 4; p++) {
        float2 a0 = upk2(o[p][0]), a1 = upk2(o[p][1]);
        float2 a2 = upk2(o[p][2]), a3 = upk2(o[p][3]);
        int ge = row0 + m0 + 2*p;
        if (ge < NN)
            *(float4*)(g_n + (long)ge * HDIM + j) = make_float4(a0.x, a1.x, a2.x, a3.x);
        if (ge + 1 < NN)
            *(float4*)(g_n + (long)(ge+1) * HDIM + j) = make_float4(a0.y, a1.y, a2.y, a3.y);
    }
}

// ---------------------------------------------------------------------------
// Edge encoder + scatter: h = relu(x@W0+b0); g_hsum[recv] += h; g_deg[recv]++
// ---------------------------------------------------------------------------
__global__ void __launch_bounds__(256) k_edge_enc_scatter(
        const float* __restrict__ x,
        const float* __restrict__ W0, const float* __restrict__ b0,
        const int* __restrict__ recvs) {
    __shared__ float A_T[16 * LDT];
    __shared__ float B_s[16 * 128];
    __shared__ int   r_idx[64];

    const int tid = threadIdx.x;
    const int ty = tid >> 5, tx = tid & 31;
    const int m0 = ty * 8;
    const int j  = tx * 4;
    const int row0 = blockIdx.x * 64;

#pragma unroll
    for (int i = 0; i < 4; i++) {
        int idx = tid + i * 256;
        int m = idx >> 4, kk = idx & 15;
        A_T[kk * LDT + m] = x[(long)(row0 + m) * 16 + kk];
    }
#pragma unroll
    for (int i = 0; i < 8; i++) B_s[tid + i * 256] = W0[tid + i * 256];
    if (tid < 64) r_idx[tid] = recvs[row0 + tid];
    __syncthreads();

    ull acc[4][4];
    {
        float4 bv = *(const float4*)(b0 + j);
#pragma unroll
        for (int p = 0; p < 4; p++) {
            acc[p][0] = pk2(bv.x, bv.x); acc[p][1] = pk2(bv.y, bv.y);
            acc[p][2] = pk2(bv.z, bv.z); acc[p][3] = pk2(bv.w, bv.w);
        }
    }
    gemm2r_step<16>(A_T, B_s, m0, j, acc);

#pragma unroll
    for (int p = 0; p < 4; p++) {
        float2 a0 = upk2(acc[p][0]), a1 = upk2(acc[p][1]);
        float2 a2 = upk2(acc[p][2]), a3 = upk2(acc[p][3]);
        int re = r_idx[m0 + 2*p], ro = r_idx[m0 + 2*p + 1];
        float* de = g_hsum + (long)re * HDIM + j;
        float* dp = g_hsum + (long)ro * HDIM + j;
        asm volatile("red.global.add.v4.f32 [%0], {%1, %2, %3, %4};"
                     :: "l"(de), "f"(fmaxf(a0.x,0.f)), "f"(fmaxf(a1.x,0.f)),
                        "f"(fmaxf(a2.x,0.f)), "f"(fmaxf(a3.x,0.f)) : "memory");
        asm volatile("red.global.add.v4.f32 [%0], {%1, %2, %3, %4};"
                     :: "l"(dp), "f"(fmaxf(a0.y,0.f)), "f"(fmaxf(a1.y,0.f)),
                        "f"(fmaxf(a2.y,0.f)), "f"(fmaxf(a3.y,0.f)) : "memory");
        if (tx == 0) { atomicAdd(g_deg + re, 1.0f); atomicAdd(g_deg + ro, 1.0f); }
    }
}

// ---------------------------------------------------------------------------
// c_agg = g_hsum @ g_Wg + g_deg * g_bg
// ---------------------------------------------------------------------------
__global__ void k_cagg() {
    extern __shared__ char smraw[];
    float* A_T = (float*)smraw;                       // [32][68]
    float* B_s = (float*)(smraw + 32 * LDT * 4);      // [32][128]

    const int tid = threadIdx.x;
    const int ty = tid >> 5, tx = tid & 31;
    const int m0 = ty * 8;
    const int j  = tx * 4;
    const int row0 = blockIdx.x * 64;

    ull acc[4][4];
    {
        float4 bgv = *(const float4*)(g_bg + j);
#pragma unroll
        for (int p = 0; p < 4; p++) {
            int ge = row0 + m0 + 2*p;
            float de = (ge     < NN) ? g_deg[ge]     : 0.f;
            float dd = (ge + 1 < NN) ? g_deg[ge + 1] : 0.f;
            acc[p][0] = pk2(de * bgv.x, dd * bgv.x);
            acc[p][1] = pk2(de * bgv.y, dd * bgv.y);
            acc[p][2] = pk2(de * bgv.z, dd * bgv.z);
            acc[p][3] = pk2(de * bgv.w, dd * bgv.w);
        }
    }
    for (int c = 0; c < 4; c++) {
        __syncthreads();
        fill_AT32<HDIM>(A_T, g_hsum, row0, c * 32, tid);
#pragma unroll
        for (int i = 0; i < 16; i++) B_s[tid + i * 256] = g_Wg[c * 32 * 128 + tid + i * 256];
        __syncthreads();
        gemm2r_step<32>(A_T, B_s, m0, j, acc);
    }
#pragma unroll
    for (int p = 0; p < 4; p++) {
        float2 a0 = upk2(acc[p][0]), a1 = upk2(acc[p][1]);
        float2 a2 = upk2(acc[p][2]), a3 = upk2(acc[p][3]);
        int ge = row0 + m0 + 2*p;
        if (ge < NN)
            *(float4*)(g_cagg + (long)ge * HDIM + j) = make_float4(a0.x, a1.x, a2.x, a3.x);
        if (ge + 1 < NN)
            *(float4*)(g_cagg + (long)(ge+1) * HDIM + j) = make_float4(a0.y, a1.y, a2.y, a3.y);
    }
}

// ---------------------------------------------------------------------------
// Per-pass scatter: S[recv] += n[sender]    (pure L2 gather/atomic)
// ---------------------------------------------------------------------------
__global__ void __launch_bounds__(256) k_scatter_n(const int* __restrict__ senders,
                                                   const int* __restrict__ recvs) {
    const int e    = blockIdx.x * 8 + (threadIdx.x >> 5);
    const int lane = threadIdx.x & 31;
    const int j = lane * 4;
    const int s = __ldg(senders + e);
    const int r = __ldg(recvs + e);
    float4 v = *(const float4*)(g_n + (long)s * HDIM + j);
    float* dst = g_S + (long)r * HDIM + j;
    asm volatile("red.global.add.v4.f32 [%0], {%1, %2, %3, %4};"
                 :: "l"(dst), "f"(v.x), "f"(v.y), "f"(v.z), "f"(v.w) : "memory");
}

// ---------------------------------------------------------------------------
// Per-pass node update (residual GEMM fused into hidden loop):
//   h = relu(n@W0_top + S@Wf + c_agg + b0); o = h@W1+b1; n' = LN(n@Wn + o)*g+b
// ---------------------------------------------------------------------------
__global__ void k_node_upd(const float* __restrict__ W0, const float* __restrict__ b0,
                           const float* __restrict__ W1, const float* __restrict__ b1,
                           const float* __restrict__ Wn,
                           const float* __restrict__ lng, const float* __restrict__ lnb) {
    extern __shared__ char smraw[];
    float* A_T  = (float*)(smraw + OFF_AT);
    float* h_s  = (float*)(smraw + OFF_H);
    float* B_s  = (float*)(smraw + OFF_B);
    float* B2_s = (float*)(smraw + OFF_B2);

    const int tid = threadIdx.x;
    const int ty = tid >> 5, tx = tid & 31;
    const int m0 = ty * 8;
    const int j  = tx * 4;
    const int row0 = blockIdx.x * 64;

    // hidden: K = 256 over [n | S]; residual rr fused on c<4 (shares A_T = n)
    ull acc[4][4], rr[4][4];
    {
        float4 bv = *(const float4*)(b0 + j);
#pragma unroll
        for (int p = 0; p < 4; p++) {
            int ge = row0 + m0 + 2*p;
            float4 ce = (ge     < NN) ? *(const float4*)(g_cagg + (long)ge * HDIM + j)
                                      : make_float4(0.f,0.f,0.f,0.f);
            float4 co = (ge + 1 < NN) ? *(const float4*)(g_cagg + (long)(ge+1) * HDIM + j)
                                      : make_float4(0.f,0.f,0.f,0.f);
            acc[p][0] = pk2(bv.x + ce.x, bv.x + co.x);
            acc[p][1] = pk2(bv.y + ce.y, bv.y + co.y);
            acc[p][2] = pk2(bv.z + ce.z, bv.z + co.z);
            acc[p][3] = pk2(bv.w + ce.w, bv.w + co.w);
            rr[p][0] = 0ull; rr[p][1] = 0ull; rr[p][2] = 0ull; rr[p][3] = 0ull;
        }
    }
    for (int c = 0; c < 8; c++) {
        const float* src  = (c < 4) ? g_n : g_S;
        const float* Bsrc = (c < 4) ? (W0 + c * 32 * 128) : (g_Wf + (c - 4) * 32 * 128);
        __syncthreads();
        fill_AT32<HDIM>(A_T, src, row0, (c & 3) * 32, tid);
#pragma unroll
        for (int i = 0; i < 16; i++) B_s[tid + i * 256] = Bsrc[tid + i * 256];
        if (c < 4) {
#pragma unroll
            for (int i = 0; i < 16; i++) B2_s[tid + i * 256] = Wn[c * 32 * 128 + tid + i * 256];
        }
        __syncthreads();
        gemm2r_step<32>(A_T, B_s, m0, j, acc);
        if (c < 4) gemm2r_step<32>(A_T, B2_s, m0, j, rr);
    }
    __syncthreads();
#pragma unroll
    for (int p = 0; p < 4; p++) {
        float2 a0 = upk2(acc[p][0]), a1 = upk2(acc[p][1]);
        float2 a2 = upk2(acc[p][2]), a3 = upk2(acc[p][3]);
        *(float4*)(h_s + (m0 + 2*p    ) * 132 + j) =
            make_float4(fmaxf(a0.x,0.f), fmaxf(a1.x,0.f), fmaxf(a2.x,0.f), fmaxf(a3.x,0.f));
        *(float4*)(h_s + (m0 + 2*p + 1) * 132 + j) =
            make_float4(fmaxf(a0.y,0.f), fmaxf(a1.y,0.f), fmaxf(a2.y,0.f), fmaxf(a3.y,0.f));
    }

    // output: K = 128
    ull o[4][4];
    {
        float4 bv = *(const float4*)(b1 + j);
#pragma unroll
        for (int p = 0; p < 4; p++) {
            o[p][0] = pk2(bv.x, bv.x); o[p][1] = pk2(bv.y, bv.y);
            o[p][2] = pk2(bv.z, bv.z); o[p][3] = pk2(bv.w, bv.w);
        }
    }
    for (int c = 0; c < 4; c++) {
        __syncthreads();
        fill_AT32_h(A_T, h_s, c, tid);
#pragma unroll
        for (int i = 0; i < 16; i++) B_s[tid + i * 256] = W1[c * 32 * 128 + tid + i * 256];
        __syncthreads();
        gemm2r_step<32>(A_T, B_s, m0, j, o);
    }

    // LayerNorm epilogue — packed: both rows of a pair reduced together
    float4 gv  = *(const float4*)(lng + j);
    float4 bbv = *(const float4*)(lnb + j);
#pragma unroll
    for (int p = 0; p < 4; p++) {
        ull t0 = add2(o[p][0], rr[p][0]);
        ull t1 = add2(o[p][1], rr[p][1]);
        ull t2 = add2(o[p][2], rr[p][2]);
        ull t3 = add2(o[p][3], rr[p][3]);
        ull s1 = add2(add2(t0, t1), add2(t2, t3));
        ull s2 = 0ull;
        FMA2(s2, t0, t0); FMA2(s2, t1, t1); FMA2(s2, t2, t2); FMA2(s2, t3, t3);
#pragma unroll
        for (int off = 16; off > 0; off >>= 1) {
            s1 = add2(s1, __shfl_xor_sync(0xffffffffu, s1, off));
            s2 = add2(s2, __shfl_xor_sync(0xffffffffu, s2, off));
        }
        float2 S1 = upk2(s1), S2 = upk2(s2);
        float mu_e  = S1.x * (1.f/128.f), mu_o  = S1.y * (1.f/128.f);
        float var_e = S2.x * (1.f/128.f) - mu_e * mu_e;
        float var_o = S2.y * (1.f/128.f) - mu_o * mu_o;
        float inv_e = rsqrtf(var_e + LN_EPS);
        float inv_o = rsqrtf(var_o + LN_EPS);
        float2 T0 = upk2(t0), T1 = upk2(t1), T2 = upk2(t2), T3 = upk2(t3);
        int ge = row0 + m0 + 2*p;
        if (ge < NN) {
            float4 out;
            out.x = (T0.x - mu_e) * inv_e * gv.x + bbv.x;
            out.y = (T1.x - mu_e) * inv_e * gv.y + bbv.y;
            out.z = (T2.x - mu_e) * inv_e * gv.z + bbv.z;
            out.w = (T3.x - mu_e) * inv_e * gv.w + bbv.w;
            *(float4*)(g_n + (long)ge * HDIM + j) = out;
        }
        if (ge + 1 < NN) {
            float4 out;
            out.x = (T0.y - mu_o) * inv_o * gv.x + bbv.x;
            out.y = (T1.y - mu_o) * inv_o * gv.y + bbv.y;
            out.z = (T2.y - mu_o) * inv_o * gv.z + bbv.z;
            out.w = (T3.y - mu_o) * inv_o * gv.w + bbv.w;
            *(float4*)(g_n + (long)(ge+1) * HDIM + j) = out;
        }
    }
}

// ---------------------------------------------------------------------------
// Decoder: out = relu(n @ W0 + b0) @ W1 + b1       out: [NN,2]
// ---------------------------------------------------------------------------
__global__ void k_dec(const float* __restrict__ W0, const float* __restrict__ b0,
                      const float* __restrict__ W1, const float* __restrict__ b1,
                      float* __restrict__ out) {
    extern __shared__ char smraw[];
    float* A_T  = (float*)(smraw + OFF_AT);
    float* h_s  = (float*)(smraw + OFF_H);
    float* B_s  = (float*)(smraw + OFF_B);
    float* w1_s = (float*)(smraw + SM_ENC);        // [256]
    float* b1_s = w1_s + 256;                      // [2]

    const int tid = threadIdx.x;
    const int ty = tid >> 5, tx = tid & 31;
    const int m0 = ty * 8;
    const int j  = tx * 4;
    const int row0 = blockIdx.x * 64;

    ull acc[4][4];
    {
        float4 bv = *(const float4*)(b0 + j);
#pragma unroll
        for (int p = 0; p < 4; p++) {
            acc[p][0] = pk2(bv.x, bv.x); acc[p][1] = pk2(bv.y, bv.y);
            acc[p][2] = pk2(bv.z, bv.z); acc[p][3] = pk2(bv.w, bv.w);
        }
    }
    for (int c = 0; c < 4; c++) {
        __syncthreads();
        fill_AT32<HDIM>(A_T, g_n, row0, c * 32, tid);
#pragma unroll
        for (int i = 0; i < 16; i++) B_s[tid + i * 256] = W0[c * 32 * 128 + tid + i * 256];
        __syncthreads();
        gemm2r_step<32>(A_T, B_s, m0, j, acc);
    }
    __syncthreads();
#pragma unroll
    for (int p = 0; p < 4; p++) {
        float2 a0 = upk2(acc[p][0]), a1 = upk2(acc[p][1]);
        float2 a2 = upk2(acc[p][2]), a3 = upk2(acc[p][3]);
        *(float4*)(h_s + (m0 + 2*p    ) * 132 + j) =
            make_float4(fmaxf(a0.x,0.f), fmaxf(a1.x,0.f), fmaxf(a2.x,0.f), fmaxf(a3.x,0.f));
        *(float4*)(h_s + (m0 + 2*p + 1) * 132 + j) =
            make_float4(fmaxf(a0.y,0.f), fmaxf(a1.y,0.f), fmaxf(a2.y,0.f), fmaxf(a3.y,0.f));
    }
    w1_s[tid] = W1[tid];
    if (tid < 2) b1_s[tid] = b1[tid];
    __syncthreads();

    if (tid < 128) {
        int row = tid >> 1, c = tid & 1;
        float s = b1_s[c];
#pragma unroll 8
        for (int k = 0; k < 128; k++)
            s = fmaf(h_s[row * 132 + k], w1_s[k * 2 + c], s);
        int gr = row0 + row;
        if (gr < NN) out[gr * 2 + c] = s;
    }
}

// ---------------------------------------------------------------------------
extern "C" void kernel_launch(void* const* d_in, const int* in_sizes, int n_in,
                              void* d_out, int out_size) {
    const float* nodes   = (const float*)d_in[0];
    const float* edges   = (const float*)d_in[1];
    const int*   senders = (const int*)  d_in[2];
    const int*   recvs   = (const int*)  d_in[3];
    const float* enW0 = (const float*)d_in[4];
    const float* enb0 = (const float*)d_in[5];
    const float* enW1 = (const float*)d_in[6];
    const float* enb1 = (const float*)d_in[7];
    const float* eeW0 = (const float*)d_in[8];
    const float* eeb0 = (const float*)d_in[9];
    const float* eeW1 = (const float*)d_in[10];
    const float* eeb1 = (const float*)d_in[11];
    const float* Wmsg = (const float*)d_in[12];
    const float* nW0  = (const float*)d_in[13];
    const float* nb0  = (const float*)d_in[14];
    const float* nW1  = (const float*)d_in[15];
    const float* nb1  = (const float*)d_in[16];
    const float* Wnode= (const float*)d_in[17];
    const float* lng  = (const float*)d_in[18];
    const float* lnb  = (const float*)d_in[19];
    const float* dW0  = (const float*)d_in[20];
    const float* db0  = (const float*)d_in[21];
    const float* dW1  = (const float*)d_in[22];
    const float* db1  = (const float*)d_in[23];
    float* out = (float*)d_out;

    const int SM_CAGG = 32 * LDT * 4 + 32 * 128 * 4;  // 25088
    const int SM_DEC  = SM_ENC + 258 * 4;             // 59912

    cudaFuncSetAttribute(k_node_enc, cudaFuncAttributeMaxDynamicSharedMemorySize, SM_ENC);
    cudaFuncSetAttribute(k_cagg,     cudaFuncAttributeMaxDynamicSharedMemorySize, SM_CAGG);
    cudaFuncSetAttribute(k_node_upd, cudaFuncAttributeMaxDynamicSharedMemorySize, SM_UPD);
    cudaFuncSetAttribute(k_dec,      cudaFuncAttributeMaxDynamicSharedMemorySize, SM_DEC);

    // Folds + invariants
    k_fold1<<<129, 128>>>(eeW1, eeb1, Wmsg);
    k_fold2<<<257, 128>>>(nW0, Wmsg);
    k_zero_pre<<<(NN * 32 + NN / 4 + 255) / 256, 256>>>();
    k_node_enc<<<NODE_TILES, 256, SM_ENC>>>(nodes, enW0, enb0, enW1, enb1);
    k_edge_enc_scatter<<<EDGE_TILES, 256>>>(edges, eeW0, eeb0, recvs);
    k_cagg<<<NODE_TILES, 256, SM_CAGG>>>();

    for (int p = 0; p < NPASS; p++) {
        k_zero_S<<<(NN * 32 + 255) / 256, 256>>>();
        k_scatter_n<<<NEDGE / 8, 256>>>(senders, recvs);
        k_node_upd<<<NODE_TILES, 256, SM_UPD>>>(nW0, nb0, nW1, nb1, Wnode, lng, lnb);
    }

    k_dec<<<NODE_TILES, 256, SM_DEC>>>(dW0, db0, dW1, db1, out);
}

// round 7
// speedup vs baseline: 1.7172x; 1.7172x over previous
#include <cuda_runtime.h>
#include <cuda_bf16.h>
#include <math.h>

#define NN     50000
#define NEDGE  600000
#define HDIM   128
#define NPASS  5
#define LN_EPS 1e-6f

#define NODE_TILES ((NN + 63) / 64)     // 782  (scalar kernels)
#define NT128      ((NN + 127) / 128)   // 391  (mma node_upd)
#define EDGE_TILES (NEDGE / 64)         // 9375

typedef unsigned int uint32;
typedef unsigned short ushort16;

// Persistent device scratch
__device__ float g_n[NN * HDIM];
__device__ float g_S[NN * HDIM];
__device__ float g_hsum[NN * HDIM];
__device__ float g_deg[NN];
__device__ float g_cagg[NN * HDIM];
__device__ float g_T1[HDIM * HDIM];     // W1e @ Wm_bot
__device__ float g_tvec[HDIM];          // b1e @ Wm_bot
__device__ float g_Wg[HDIM * HDIM];     // (W1e @ Wm_bot) @ W0_bot
__device__ float g_bg[HDIM];

// Split-bf16 weight tables, [N][K] k-contiguous (transposed)
__device__ __align__(16) ushort16 g_BtopH[HDIM * HDIM], g_BtopL[HDIM * HDIM]; // W0_top
__device__ __align__(16) ushort16 g_BWfH [HDIM * HDIM], g_BWfL [HDIM * HDIM]; // Wm_top@W0_bot
__device__ __align__(16) ushort16 g_BresH[HDIM * HDIM], g_BresL[HDIM * HDIM]; // Wn
__device__ __align__(16) ushort16 g_BoutH[HDIM * HDIM], g_BoutL[HDIM * HDIM]; // W1

// ---------------------------------------------------------------------------
// Scalar register-tiled GEMM micro-step (R3 proven) — used by enc/cagg/dec
// ---------------------------------------------------------------------------
template<int KC, int LDA>
__device__ __forceinline__ void gemm_step(const float* __restrict__ A_s,
                                          const float* __restrict__ B_s,
                                          int m0, int j, float acc[8][4]) {
#pragma unroll 8
    for (int kk = 0; kk < KC; kk++) {
        float4 b = *(const float4*)(B_s + kk * HDIM + j);
#pragma unroll
        for (int r = 0; r < 8; r++) {
            float a = A_s[(m0 + r) * LDA + kk];
            acc[r][0] = fmaf(a, b.x, acc[r][0]);
            acc[r][1] = fmaf(a, b.y, acc[r][1]);
            acc[r][2] = fmaf(a, b.z, acc[r][2]);
            acc[r][3] = fmaf(a, b.w, acc[r][3]);
        }
    }
}

// ---------------------------------------------------------------------------
// bf16 helpers + MMA
// ---------------------------------------------------------------------------
__device__ __forceinline__ uint32 pack_bf2(float x, float y) {
    __nv_bfloat162 t = __floats2bfloat162_rn(x, y);
    return *reinterpret_cast<uint32*>(&t);
}
__device__ __forceinline__ void split_bf(float v, ushort16& h, ushort16& l) {
    __nv_bfloat16 hb = __float2bfloat16_rn(v);
    float lo = v - __bfloat162float(hb);
    __nv_bfloat16 lb = __float2bfloat16_rn(lo);
    h = *reinterpret_cast<ushort16*>(&hb);
    l = *reinterpret_cast<ushort16*>(&lb);
}
#define MMA16816(d, a0,a1,a2,a3, b0,b1) \
    asm volatile("mma.sync.aligned.m16n8k16.row.col.f32.bf16.bf16.f32 " \
        "{%0,%1,%2,%3},{%4,%5,%6,%7},{%8,%9},{%0,%1,%2,%3};" \
        : "+f"((d)[0]), "+f"((d)[1]), "+f"((d)[2]), "+f"((d)[3]) \
        : "r"(a0), "r"(a1), "r"(a2), "r"(a3), "r"(b0), "r"(b1))

// ---------------------------------------------------------------------------
// Weight folds
// ---------------------------------------------------------------------------
__global__ void k_fold1(const float* __restrict__ W1e, const float* __restrict__ b1e,
                        const float* __restrict__ Wm) {
    __shared__ float a[HDIM];
    int j = threadIdx.x;
    a[j] = (blockIdx.x < 128) ? W1e[blockIdx.x * HDIM + j] : b1e[j];
    __syncthreads();
    float s = 0.f;
#pragma unroll 8
    for (int l = 0; l < HDIM; l++)
        s = fmaf(a[l], Wm[(HDIM + l) * HDIM + j], s);
    if (blockIdx.x < 128) g_T1[blockIdx.x * HDIM + j] = s;
    else                  g_tvec[j] = s;
}

// bid<128: Wg rows; bid==128: bg; bid>=129: Wf row (k=bid-129) -> split/transposed
__global__ void k_fold2(const float* __restrict__ W0n, const float* __restrict__ Wm) {
    __shared__ float a[HDIM];
    int j = threadIdx.x;
    int bid = blockIdx.x;
    if (bid < 128)       a[j] = g_T1[bid * HDIM + j];
    else if (bid == 128) a[j] = g_tvec[j];
    else                 a[j] = Wm[(bid - 129) * HDIM + j];
    __syncthreads();
    float s = 0.f;
#pragma unroll 8
    for (int l = 0; l < HDIM; l++)
        s = fmaf(a[l], W0n[(HDIM + l) * HDIM + j], s);
    if (bid < 128)       g_Wg[bid * HDIM + j] = s;
    else if (bid == 128) g_bg[j] = s;
    else {
        int k = bid - 129;
        ushort16 h, l2; split_bf(s, h, l2);
        g_BWfH[j * HDIM + k] = h;   // [n][k]
        g_BWfL[j * HDIM + k] = l2;
    }
}

// Split + transpose a [128][128] fp32 weight into [N][K] bf16 hi/lo.
// `which` selects the destination table IN DEVICE CODE (never pass __device__
// array addresses from host — that was the R6 bug).
__global__ void k_splitB(const float* __restrict__ W, int which) {
    ushort16* dH; ushort16* dL;
    if (which == 0)      { dH = g_BtopH; dL = g_BtopL; }
    else if (which == 1) { dH = g_BresH; dL = g_BresL; }
    else                 { dH = g_BoutH; dL = g_BoutL; }
    int idx = blockIdx.x * 256 + threadIdx.x;   // 16384
    int k = idx >> 7, n = idx & 127;
    ushort16 h, l;
    split_bf(W[k * HDIM + n], h, l);
    dH[n * HDIM + k] = h;
    dL[n * HDIM + k] = l;
}

// ---------------------------------------------------------------------------
// Zero helpers
// ---------------------------------------------------------------------------
__global__ void k_zero_pre() {
    int i = blockIdx.x * blockDim.x + threadIdx.x;
    if (i < NN * 32) ((float4*)g_hsum)[i] = make_float4(0.f, 0.f, 0.f, 0.f);
    else {
        int d = i - NN * 32;
        if (d < NN / 4) ((float4*)g_deg)[d] = make_float4(0.f, 0.f, 0.f, 0.f);
    }
}
__global__ void k_zero_S() {
    int i = blockIdx.x * blockDim.x + threadIdx.x;
    if (i < NN * 32) ((float4*)g_S)[i] = make_float4(0.f, 0.f, 0.f, 0.f);
}

// ---------------------------------------------------------------------------
// Node encoder (scalar, R3): n = relu(x@W0+b0)@W1+b1
// ---------------------------------------------------------------------------
__global__ void k_node_enc(const float* __restrict__ x,
                           const float* __restrict__ W0, const float* __restrict__ b0,
                           const float* __restrict__ W1, const float* __restrict__ b1) {
    extern __shared__ float sm[];
    float* h_s = sm;                 // [64][132]
    float* B_s = sm + 64 * 132;      // [32][128]
    float* A_s = sm;                 // union, [64][33]

    const int tid = threadIdx.x;
    const int ty = tid >> 5, tx = tid & 31;
    const int m0 = ty * 8;
    const int j  = tx * 4;
    const int row0 = blockIdx.x * 64;

#pragma unroll
    for (int i = 0; i < 8; i++) {
        int idx = tid + i * 256;
        int m = idx >> 5, kk = idx & 31;
        int gr = row0 + m;
        A_s[m * 33 + kk] = (gr < NN) ? x[gr * 32 + kk] : 0.f;
    }
#pragma unroll
    for (int i = 0; i < 16; i++) B_s[tid + i * 256] = W0[tid + i * 256];
    __syncthreads();

    float acc[8][4];
    {
        float4 bv = *(const float4*)(b0 + j);
#pragma unroll
        for (int r = 0; r < 8; r++) { acc[r][0]=bv.x; acc[r][1]=bv.y; acc[r][2]=bv.z; acc[r][3]=bv.w; }
    }
    gemm_step<32, 33>(A_s, B_s, m0, j, acc);
    __syncthreads();

#pragma unroll
    for (int r = 0; r < 8; r++) {
        float4 h;
        h.x = fmaxf(acc[r][0], 0.f); h.y = fmaxf(acc[r][1], 0.f);
        h.z = fmaxf(acc[r][2], 0.f); h.w = fmaxf(acc[r][3], 0.f);
        *(float4*)(h_s + (m0 + r) * 132 + j) = h;
    }

    float o[8][4];
    {
        float4 bv = *(const float4*)(b1 + j);
#pragma unroll
        for (int r = 0; r < 8; r++) { o[r][0]=bv.x; o[r][1]=bv.y; o[r][2]=bv.z; o[r][3]=bv.w; }
    }
    for (int c = 0; c < 4; c++) {
        __syncthreads();
#pragma unroll
        for (int i = 0; i < 16; i++) B_s[tid + i * 256] = W1[c * 32 * 128 + tid + i * 256];
        __syncthreads();
        gemm_step<32, 132>(h_s + c * 32, B_s, m0, j, o);
    }
#pragma unroll
    for (int r = 0; r < 8; r++) {
        int gr = row0 + m0 + r;
        if (gr < NN)
            *(float4*)(g_n + gr * HDIM + j) = make_float4(o[r][0], o[r][1], o[r][2], o[r][3]);
    }
}

// ---------------------------------------------------------------------------
// Edge encoder + scatter (scalar, R3)
// ---------------------------------------------------------------------------
__global__ void __launch_bounds__(256) k_edge_enc_scatter(
        const float* __restrict__ x,
        const float* __restrict__ W0, const float* __restrict__ b0,
        const int* __restrict__ recvs) {
    __shared__ float A_s[64 * 17];
    __shared__ float B_s[16 * 128];
    __shared__ int   r_idx[64];

    const int tid = threadIdx.x;
    const int ty = tid >> 5, tx = tid & 31;
    const int m0 = ty * 8;
    const int j  = tx * 4;
    const int row0 = blockIdx.x * 64;

#pragma unroll
    for (int i = 0; i < 4; i++) {
        int idx = tid + i * 256;
        int m = idx >> 4, kk = idx & 15;
        A_s[m * 17 + kk] = x[(long)(row0 + m) * 16 + kk];
    }
#pragma unroll
    for (int i = 0; i < 8; i++) B_s[tid + i * 256] = W0[tid + i * 256];
    if (tid < 64) r_idx[tid] = recvs[row0 + tid];
    __syncthreads();

    float acc[8][4];
    {
        float4 bv = *(const float4*)(b0 + j);
#pragma unroll
        for (int r = 0; r < 8; r++) { acc[r][0]=bv.x; acc[r][1]=bv.y; acc[r][2]=bv.z; acc[r][3]=bv.w; }
    }
    gemm_step<16, 17>(A_s, B_s, m0, j, acc);

#pragma unroll
    for (int r = 0; r < 8; r++) {
        int rv = r_idx[m0 + r];
        float v0 = fmaxf(acc[r][0], 0.f), v1 = fmaxf(acc[r][1], 0.f);
        float v2 = fmaxf(acc[r][2], 0.f), v3 = fmaxf(acc[r][3], 0.f);
        float* dst = g_hsum + (long)rv * HDIM + j;
        asm volatile("red.global.add.v4.f32 [%0], {%1, %2, %3, %4};"
                     :: "l"(dst), "f"(v0), "f"(v1), "f"(v2), "f"(v3) : "memory");
        if (tx == 0) atomicAdd(g_deg + rv, 1.0f);
    }
}

// ---------------------------------------------------------------------------
// c_agg = g_hsum @ g_Wg + g_deg * g_bg  (scalar, R3)
// ---------------------------------------------------------------------------
__global__ void k_cagg() {
    extern __shared__ float sm[];
    float* A_s = sm;                 // [64][33]
    float* B_s = sm + 64 * 33;       // [32][128]

    const int tid = threadIdx.x;
    const int ty = tid >> 5, tx = tid & 31;
    const int m0 = ty * 8;
    const int j  = tx * 4;
    const int row0 = blockIdx.x * 64;

    float acc[8][4];
    {
        float4 bgv = *(const float4*)(g_bg + j);
#pragma unroll
        for (int r = 0; r < 8; r++) {
            int gr = row0 + m0 + r;
            float d = (gr < NN) ? g_deg[gr] : 0.f;
            acc[r][0] = d * bgv.x; acc[r][1] = d * bgv.y;
            acc[r][2] = d * bgv.z; acc[r][3] = d * bgv.w;
        }
    }
    for (int c = 0; c < 4; c++) {
        __syncthreads();
#pragma unroll
        for (int i = 0; i < 8; i++) {
            int idx = tid + i * 256;
            int m = idx >> 5, kk = idx & 31;
            int gr = row0 + m;
            A_s[m * 33 + kk] = (gr < NN) ? g_hsum[gr * HDIM + c * 32 + kk] : 0.f;
        }
#pragma unroll
        for (int i = 0; i < 16; i++) B_s[tid + i * 256] = g_Wg[c * 32 * 128 + tid + i * 256];
        __syncthreads();
        gemm_step<32, 33>(A_s, B_s, m0, j, acc);
    }
#pragma unroll
    for (int r = 0; r < 8; r++) {
        int gr = row0 + m0 + r;
        if (gr < NN)
            *(float4*)(g_cagg + gr * HDIM + j) =
                make_float4(acc[r][0], acc[r][1], acc[r][2], acc[r][3]);
    }
}

// ---------------------------------------------------------------------------
// Per-pass scatter: S[recv] += n[sender]
// ---------------------------------------------------------------------------
__global__ void __launch_bounds__(256) k_scatter_n(const int* __restrict__ senders,
                                                   const int* __restrict__ recvs) {
    const int e    = blockIdx.x * 8 + (threadIdx.x >> 5);
    const int lane = threadIdx.x & 31;
    const int j = lane * 4;
    const int s = __ldg(senders + e);
    const int r = __ldg(recvs + e);
    float4 v = *(const float4*)(g_n + (long)s * HDIM + j);
    float* dst = g_S + (long)r * HDIM + j;
    asm volatile("red.global.add.v4.f32 [%0], {%1, %2, %3, %4};"
                 :: "l"(dst), "f"(v.x), "f"(v.y), "f"(v.z), "f"(v.w) : "memory");
}

// ===========================================================================
// MMA node update. Block = 128 rows x 128 cols, 8 warps (16 rows each).
// ===========================================================================
#define U_AH 0
#define U_AL (U_AH + 128 * 18)
#define U_BH (U_AL + 128 * 18)
#define U_BL (U_BH + 128 * 18)
#define U_HH (U_BL + 128 * 18)
#define U_HL (U_HH + 128 * 68)
#define U_END (U_HL + 128 * 68)
#define SM_MMA (U_END * 4)          // 106496 bytes

__device__ __forceinline__ void fillA(uint32* AhU, uint32* AlU,
                                      const float* __restrict__ src,
                                      int row0, int koff, int tid) {
#pragma unroll
    for (int i = 0; i < 8; i++) {
        int p = tid + i * 256;              // 2048 = 128 rows x 16 u32
        int row = p >> 4, kw = p & 15;
        int gr = row0 + row;
        float2 v = make_float2(0.f, 0.f);
        if (gr < NN) v = *(const float2*)(src + (long)gr * HDIM + koff + 2 * kw);
        float hx = __bfloat162float(__float2bfloat16_rn(v.x));
        float hy = __bfloat162float(__float2bfloat16_rn(v.y));
        AhU[row * 18 + kw] = pack_bf2(v.x, v.y);
        AlU[row * 18 + kw] = pack_bf2(v.x - hx, v.y - hy);
    }
}

__device__ __forceinline__ void fillB(uint32* BhU, uint32* BlU,
                                      const ushort16* __restrict__ gH,
                                      const ushort16* __restrict__ gL,
                                      int koff, int tid) {
    const uint32* sH = (const uint32*)gH;   // [n][64] u32
    const uint32* sL = (const uint32*)gL;
#pragma unroll
    for (int i = 0; i < 8; i++) {
        int p = tid + i * 256;
        int n = p >> 4, kw = p & 15;
        BhU[n * 18 + kw] = sH[n * 64 + (koff >> 1) + kw];
        BlU[n * 18 + kw] = sL[n * 64 + (koff >> 1) + kw];
    }
}

template<int AS>
__device__ __forceinline__ void mma_chunk(const uint32* AhU, const uint32* AlU,
                                          const uint32* BhU, const uint32* BlU,
                                          float acc[16][4], int rw0, int gid, int tg) {
#pragma unroll
    for (int kb2 = 0; kb2 <= 8; kb2 += 8) {
        int a0i = (rw0 + gid) * AS + kb2 + tg;
        int a1i = a0i + 8 * AS;
        uint32 ah0 = AhU[a0i],     ah1 = AhU[a1i];
        uint32 ah2 = AhU[a0i + 4], ah3 = AhU[a1i + 4];
        uint32 al0 = AlU[a0i],     al1 = AlU[a1i];
        uint32 al2 = AlU[a0i + 4], al3 = AlU[a1i + 4];
#pragma unroll
        for (int t = 0; t < 16; t++) {
            int bi = (8 * t + gid) * 18 + kb2 + tg;
            uint32 bh0 = BhU[bi], bh1 = BhU[bi + 4];
            uint32 bl0 = BlU[bi], bl1 = BlU[bi + 4];
            MMA16816(acc[t], ah0, ah1, ah2, ah3, bh0, bh1);
            MMA16816(acc[t], ah0, ah1, ah2, ah3, bl0, bl1);
            MMA16816(acc[t], al0, al1, al2, al3, bh0, bh1);
        }
    }
}

__global__ void __launch_bounds__(256, 2) k_node_upd_mma(
        const float* __restrict__ b0, const float* __restrict__ b1,
        const float* __restrict__ lng, const float* __restrict__ lnb) {
    extern __shared__ uint32 smu[];
    uint32* AhU = smu + U_AH;
    uint32* AlU = smu + U_AL;
    uint32* BhU = smu + U_BH;
    uint32* BlU = smu + U_BL;
    uint32* HhU = smu + U_HH;
    uint32* HlU = smu + U_HL;

    const int tid = threadIdx.x;
    const int w = tid >> 5, lane = tid & 31;
    const int gid = lane >> 2, tg = lane & 3;
    const int rw0 = w * 16;
    const int row0 = blockIdx.x * 128;
    const int r_e = row0 + rw0 + gid;
    const int r_o = r_e + 8;

    float acc[16][4];

    // ---- hidden accumulator init: b0 + c_agg ----
#pragma unroll
    for (int t = 0; t < 16; t++) {
        int col = 8 * t + 2 * tg;
        float2 bb = *(const float2*)(b0 + col);
        float2 ce = (r_e < NN) ? *(const float2*)(g_cagg + (long)r_e * HDIM + col)
                               : make_float2(0.f, 0.f);
        float2 co = (r_o < NN) ? *(const float2*)(g_cagg + (long)r_o * HDIM + col)
                               : make_float2(0.f, 0.f);
        acc[t][0] = bb.x + ce.x; acc[t][1] = bb.y + ce.y;
        acc[t][2] = bb.x + co.x; acc[t][3] = bb.y + co.y;
    }

    // ---- hidden: K = 256 over [n | S] ----
    for (int c = 0; c < 8; c++) {
        const float* src = (c < 4) ? g_n : g_S;
        const ushort16* gH = (c < 4) ? g_BtopH : g_BWfH;
        const ushort16* gL = (c < 4) ? g_BtopL : g_BWfL;
        int koff = (c & 3) * 32;
        __syncthreads();
        fillA(AhU, AlU, src, row0, koff, tid);
        fillB(BhU, BlU, gH, gL, koff, tid);
        __syncthreads();
        mma_chunk<18>(AhU, AlU, BhU, BlU, acc, rw0, gid, tg);
    }

    // ---- relu + split-store h to smem H ----
#pragma unroll
    for (int t = 0; t < 16; t++) {
        float h0 = fmaxf(acc[t][0], 0.f), h1 = fmaxf(acc[t][1], 0.f);
        float h2 = fmaxf(acc[t][2], 0.f), h3 = fmaxf(acc[t][3], 0.f);
        int ie = (rw0 + gid) * 68 + 4 * t + tg;
        int io = ie + 8 * 68;
        float e0 = __bfloat162float(__float2bfloat16_rn(h0));
        float e1 = __bfloat162float(__float2bfloat16_rn(h1));
        float e2 = __bfloat162float(__float2bfloat16_rn(h2));
        float e3 = __bfloat162float(__float2bfloat16_rn(h3));
        HhU[ie] = pack_bf2(h0, h1);
        HlU[ie] = pack_bf2(h0 - e0, h1 - e1);
        HhU[io] = pack_bf2(h2, h3);
        HlU[io] = pack_bf2(h2 - e2, h3 - e3);
    }

    // ---- residual: acc = n @ Wn ----
#pragma unroll
    for (int t = 0; t < 16; t++) {
        acc[t][0] = 0.f; acc[t][1] = 0.f; acc[t][2] = 0.f; acc[t][3] = 0.f;
    }
    for (int c = 0; c < 4; c++) {
        __syncthreads();
        fillA(AhU, AlU, g_n, row0, c * 32, tid);
        fillB(BhU, BlU, g_BresH, g_BresL, c * 32, tid);
        __syncthreads();
        mma_chunk<18>(AhU, AlU, BhU, BlU, acc, rw0, gid, tg);
    }

    // ---- output: acc += h @ W1  (A from smem H) ----
    for (int c = 0; c < 4; c++) {
        __syncthreads();
        fillB(BhU, BlU, g_BoutH, g_BoutL, c * 32, tid);
        __syncthreads();
        mma_chunk<68>(HhU + 16 * c, HlU + 16 * c, BhU, BlU, acc, rw0, gid, tg);
    }

    // ---- + b1, LayerNorm (warp-local rows), write g_n ----
    float s1e = 0.f, s2e = 0.f, s1o = 0.f, s2o = 0.f;
#pragma unroll
    for (int t = 0; t < 16; t++) {
        int col = 8 * t + 2 * tg;
        float2 bb = *(const float2*)(b1 + col);
        acc[t][0] += bb.x; acc[t][1] += bb.y;
        acc[t][2] += bb.x; acc[t][3] += bb.y;
        s1e += acc[t][0] + acc[t][1];
        s2e += acc[t][0] * acc[t][0] + acc[t][1] * acc[t][1];
        s1o += acc[t][2] + acc[t][3];
        s2o += acc[t][2] * acc[t][2] + acc[t][3] * acc[t][3];
    }
#pragma unroll
    for (int off = 1; off <= 2; off <<= 1) {
        s1e += __shfl_xor_sync(0xffffffffu, s1e, off);
        s2e += __shfl_xor_sync(0xffffffffu, s2e, off);
        s1o += __shfl_xor_sync(0xffffffffu, s1o, off);
        s2o += __shfl_xor_sync(0xffffffffu, s2o, off);
    }
    float mu_e = s1e * (1.f / 128.f);
    float mu_o = s1o * (1.f / 128.f);
    float inv_e = rsqrtf(s2e * (1.f / 128.f) - mu_e * mu_e + LN_EPS);
    float inv_o = rsqrtf(s2o * (1.f / 128.f) - mu_o * mu_o + LN_EPS);

#pragma unroll
    for (int t = 0; t < 16; t++) {
        int col = 8 * t + 2 * tg;
        float2 gv = *(const float2*)(lng + col);
        float2 bv = *(const float2*)(lnb + col);
        if (r_e < NN) {
            float2 o;
            o.x = (acc[t][0] - mu_e) * inv_e * gv.x + bv.x;
            o.y = (acc[t][1] - mu_e) * inv_e * gv.y + bv.y;
            *(float2*)(g_n + (long)r_e * HDIM + col) = o;
        }
        if (r_o < NN) {
            float2 o;
            o.x = (acc[t][2] - mu_o) * inv_o * gv.x + bv.x;
            o.y = (acc[t][3] - mu_o) * inv_o * gv.y + bv.y;
            *(float2*)(g_n + (long)r_o * HDIM + col) = o;
        }
    }
}

// ---------------------------------------------------------------------------
// Decoder (scalar, R3): out = relu(n @ W0 + b0) @ W1 + b1
// ---------------------------------------------------------------------------
__global__ void k_dec(const float* __restrict__ W0, const float* __restrict__ b0,
                      const float* __restrict__ W1, const float* __restrict__ b1,
                      float* __restrict__ out) {
    extern __shared__ float sm[];
    float* h_s  = sm;                 // [64][132]
    float* B_s  = sm + 64 * 132;      // [32][128]
    float* A_s  = sm;                 // union, [64][33]
    float* w1_s = B_s + 32 * 128;     // [256]
    float* b1_s = w1_s + 256;         // [2]

    const int tid = threadIdx.x;
    const int ty = tid >> 5, tx = tid & 31;
    const int m0 = ty * 8;
    const int j  = tx * 4;
    const int row0 = blockIdx.x * 64;

    float acc[8][4];
    {
        float4 bv = *(const float4*)(b0 + j);
#pragma unroll
        for (int r = 0; r < 8; r++) { acc[r][0]=bv.x; acc[r][1]=bv.y; acc[r][2]=bv.z; acc[r][3]=bv.w; }
    }
    for (int c = 0; c < 4; c++) {
        __syncthreads();
#pragma unroll
        for (int i = 0; i < 8; i++) {
            int idx = tid + i * 256;
            int m = idx >> 5, kk = idx & 31;
            int gr = row0 + m;
            A_s[m * 33 + kk] = (gr < NN) ? g_n[gr * HDIM + c * 32 + kk] : 0.f;
        }
#pragma unroll
        for (int i = 0; i < 16; i++) B_s[tid + i * 256] = W0[c * 32 * 128 + tid + i * 256];
        __syncthreads();
        gemm_step<32, 33>(A_s, B_s, m0, j, acc);
    }
    __syncthreads();
#pragma unroll
    for (int r = 0; r < 8; r++) {
        float4 h;
        h.x = fmaxf(acc[r][0], 0.f); h.y = fmaxf(acc[r][1], 0.f);
        h.z = fmaxf(acc[r][2], 0.f); h.w = fmaxf(acc[r][3], 0.f);
        *(float4*)(h_s + (m0 + r) * 132 + j) = h;
    }
    w1_s[tid] = W1[tid];
    if (tid < 2) b1_s[tid] = b1[tid];
    __syncthreads();

    if (tid < 128) {
        int row = tid >> 1, c = tid & 1;
        float s = b1_s[c];
#pragma unroll 8
        for (int k = 0; k < 128; k++)
            s = fmaf(h_s[row * 132 + k], w1_s[k * 2 + c], s);
        int gr = row0 + row;
        if (gr < NN) out[gr * 2 + c] = s;
    }
}

// ---------------------------------------------------------------------------
extern "C" void kernel_launch(void* const* d_in, const int* in_sizes, int n_in,
                              void* d_out, int out_size) {
    const float* nodes   = (const float*)d_in[0];
    const float* edges   = (const float*)d_in[1];
    const int*   senders = (const int*)  d_in[2];
    const int*   recvs   = (const int*)  d_in[3];
    const float* enW0 = (const float*)d_in[4];
    const float* enb0 = (const float*)d_in[5];
    const float* enW1 = (const float*)d_in[6];
    const float* enb1 = (const float*)d_in[7];
    const float* eeW0 = (const float*)d_in[8];
    const float* eeb0 = (const float*)d_in[9];
    const float* eeW1 = (const float*)d_in[10];
    const float* eeb1 = (const float*)d_in[11];
    const float* Wmsg = (const float*)d_in[12];
    const float* nW0  = (const float*)d_in[13];
    const float* nb0  = (const float*)d_in[14];
    const float* nW1  = (const float*)d_in[15];
    const float* nb1  = (const float*)d_in[16];
    const float* Wnode= (const float*)d_in[17];
    const float* lng  = (const float*)d_in[18];
    const float* lnb  = (const float*)d_in[19];
    const float* dW0  = (const float*)d_in[20];
    const float* db0  = (const float*)d_in[21];
    const float* dW1  = (const float*)d_in[22];
    const float* db1  = (const float*)d_in[23];
    float* out = (float*)d_out;

    const int SM_BIG  = (64 * 132 + 32 * 128) * 4;              // 50176
    const int SM_MSG  = (64 * 33 + 32 * 128) * 4;               // 24832
    const int SM_DEC  = (64 * 132 + 32 * 128 + 256 + 2) * 4;    // 51208

    cudaFuncSetAttribute(k_node_enc,     cudaFuncAttributeMaxDynamicSharedMemorySize, SM_BIG);
    cudaFuncSetAttribute(k_cagg,         cudaFuncAttributeMaxDynamicSharedMemorySize, SM_MSG);
    cudaFuncSetAttribute(k_node_upd_mma, cudaFuncAttributeMaxDynamicSharedMemorySize, SM_MMA);
    cudaFuncSetAttribute(k_dec,          cudaFuncAttributeMaxDynamicSharedMemorySize, SM_DEC);

    // Folds, splits, invariants
    k_fold1<<<129, 128>>>(eeW1, eeb1, Wmsg);
    k_fold2<<<257, 128>>>(nW0, Wmsg);
    k_splitB<<<64, 256>>>(nW0,   0);   // W0 top half -> g_Btop
    k_splitB<<<64, 256>>>(Wnode, 1);   // -> g_Bres
    k_splitB<<<64, 256>>>(nW1,   2);   // -> g_Bout
    k_zero_pre<<<(NN * 32 + NN / 4 + 255) / 256, 256>>>();
    k_node_enc<<<NODE_TILES, 256, SM_BIG>>>(nodes, enW0, enb0, enW1, enb1);
    k_edge_enc_scatter<<<EDGE_TILES, 256>>>(edges, eeW0, eeb0, recvs);
    k_cagg<<<NODE_TILES, 256, SM_MSG>>>();

    for (int p = 0; p < NPASS; p++) {
        k_zero_S<<<(NN * 32 + 255) / 256, 256>>>();
        k_scatter_n<<<NEDGE / 8, 256>>>(senders, recvs);
        k_node_upd_mma<<<NT128, 256, SM_MMA>>>(nb0, nb1, lng, lnb);
    }

    k_dec<<<NODE_TILES, 256, SM_DEC>>>(dW0, db0, dW1, db1, out);
}

// round 8
// speedup vs baseline: 1.8278x; 1.0644x over previous
#include <cuda_runtime.h>
#include <cuda_bf16.h>
#include <math.h>

#define NN     50000
#define NEDGE  600000
#define HDIM   128
#define NPASS  5
#define LN_EPS 1e-6f

#define NODE_TILES ((NN + 63) / 64)     // 782  (scalar kernels)
#define NT128      ((NN + 127) / 128)   // 391  (mma node_upd)
#define EDGE_TILES (NEDGE / 64)         // 9375

typedef unsigned int uint32;
typedef unsigned short ushort16;

// Persistent device scratch
__device__ float g_n[NN * HDIM];
__device__ float g_S[NN * HDIM];
__device__ float g_hsum[NN * HDIM];
__device__ float g_deg[NN];
__device__ float g_cagg[NN * HDIM];
__device__ float g_T1[HDIM * HDIM];     // W1e @ Wm_bot
__device__ float g_tvec[HDIM];          // b1e @ Wm_bot
__device__ float g_Wg[HDIM * HDIM];     // (W1e @ Wm_bot) @ W0_bot
__device__ float g_bg[HDIM];

// Split-bf16 weight tables, [N][K] k-contiguous (transposed)
__device__ __align__(16) ushort16 g_BtopH[HDIM * HDIM], g_BtopL[HDIM * HDIM]; // W0_top
__device__ __align__(16) ushort16 g_BWfH [HDIM * HDIM], g_BWfL [HDIM * HDIM]; // Wm_top@W0_bot
__device__ __align__(16) ushort16 g_BresH[HDIM * HDIM], g_BresL[HDIM * HDIM]; // Wn
__device__ __align__(16) ushort16 g_BoutH[HDIM * HDIM], g_BoutL[HDIM * HDIM]; // W1

// ---------------------------------------------------------------------------
// Scalar register-tiled GEMM micro-step (R3 proven) — used by enc/cagg/dec
// ---------------------------------------------------------------------------
template<int KC, int LDA>
__device__ __forceinline__ void gemm_step(const float* __restrict__ A_s,
                                          const float* __restrict__ B_s,
                                          int m0, int j, float acc[8][4]) {
#pragma unroll 8
    for (int kk = 0; kk < KC; kk++) {
        float4 b = *(const float4*)(B_s + kk * HDIM + j);
#pragma unroll
        for (int r = 0; r < 8; r++) {
            float a = A_s[(m0 + r) * LDA + kk];
            acc[r][0] = fmaf(a, b.x, acc[r][0]);
            acc[r][1] = fmaf(a, b.y, acc[r][1]);
            acc[r][2] = fmaf(a, b.z, acc[r][2]);
            acc[r][3] = fmaf(a, b.w, acc[r][3]);
        }
    }
}

// ---------------------------------------------------------------------------
// bf16 helpers + MMA
// ---------------------------------------------------------------------------
__device__ __forceinline__ uint32 pack_bf2(float x, float y) {
    __nv_bfloat162 t = __floats2bfloat162_rn(x, y);
    return *reinterpret_cast<uint32*>(&t);
}
__device__ __forceinline__ void split_bf(float v, ushort16& h, ushort16& l) {
    __nv_bfloat16 hb = __float2bfloat16_rn(v);
    float lo = v - __bfloat162float(hb);
    __nv_bfloat16 lb = __float2bfloat16_rn(lo);
    h = *reinterpret_cast<ushort16*>(&hb);
    l = *reinterpret_cast<ushort16*>(&lb);
}
#define MMA16816(d, a0,a1,a2,a3, b0,b1) \
    asm volatile("mma.sync.aligned.m16n8k16.row.col.f32.bf16.bf16.f32 " \
        "{%0,%1,%2,%3},{%4,%5,%6,%7},{%8,%9},{%0,%1,%2,%3};" \
        : "+f"((d)[0]), "+f"((d)[1]), "+f"((d)[2]), "+f"((d)[3]) \
        : "r"(a0), "r"(a1), "r"(a2), "r"(a3), "r"(b0), "r"(b1))

// ---------------------------------------------------------------------------
// Weight folds
// ---------------------------------------------------------------------------
__global__ void k_fold1(const float* __restrict__ W1e, const float* __restrict__ b1e,
                        const float* __restrict__ Wm) {
    __shared__ float a[HDIM];
    int j = threadIdx.x;
    a[j] = (blockIdx.x < 128) ? W1e[blockIdx.x * HDIM + j] : b1e[j];
    __syncthreads();
    float s = 0.f;
#pragma unroll 8
    for (int l = 0; l < HDIM; l++)
        s = fmaf(a[l], Wm[(HDIM + l) * HDIM + j], s);
    if (blockIdx.x < 128) g_T1[blockIdx.x * HDIM + j] = s;
    else                  g_tvec[j] = s;
}

// bid<128: Wg rows; bid==128: bg; bid>=129: Wf row (k=bid-129) -> split/transposed
__global__ void k_fold2(const float* __restrict__ W0n, const float* __restrict__ Wm) {
    __shared__ float a[HDIM];
    int j = threadIdx.x;
    int bid = blockIdx.x;
    if (bid < 128)       a[j] = g_T1[bid * HDIM + j];
    else if (bid == 128) a[j] = g_tvec[j];
    else                 a[j] = Wm[(bid - 129) * HDIM + j];
    __syncthreads();
    float s = 0.f;
#pragma unroll 8
    for (int l = 0; l < HDIM; l++)
        s = fmaf(a[l], W0n[(HDIM + l) * HDIM + j], s);
    if (bid < 128)       g_Wg[bid * HDIM + j] = s;
    else if (bid == 128) g_bg[j] = s;
    else {
        int k = bid - 129;
        ushort16 h, l2; split_bf(s, h, l2);
        g_BWfH[j * HDIM + k] = h;   // [n][k]
        g_BWfL[j * HDIM + k] = l2;
    }
}

// Split + transpose a [128][128] fp32 weight into [N][K] bf16 hi/lo.
// `which` selects the destination table IN DEVICE CODE (R6 lesson: never pass
// __device__ array addresses from host).
__global__ void k_splitB(const float* __restrict__ W, int which) {
    ushort16* dH; ushort16* dL;
    if (which == 0)      { dH = g_BtopH; dL = g_BtopL; }
    else if (which == 1) { dH = g_BresH; dL = g_BresL; }
    else                 { dH = g_BoutH; dL = g_BoutL; }
    int idx = blockIdx.x * 256 + threadIdx.x;   // 16384
    int k = idx >> 7, n = idx & 127;
    ushort16 h, l;
    split_bf(W[k * HDIM + n], h, l);
    dH[n * HDIM + k] = h;
    dL[n * HDIM + k] = l;
}

// ---------------------------------------------------------------------------
// Zero helpers
// ---------------------------------------------------------------------------
__global__ void k_zero_pre() {
    int i = blockIdx.x * blockDim.x + threadIdx.x;
    if (i < NN * 32) ((float4*)g_hsum)[i] = make_float4(0.f, 0.f, 0.f, 0.f);
    else {
        int d = i - NN * 32;
        if (d < NN / 4) ((float4*)g_deg)[d] = make_float4(0.f, 0.f, 0.f, 0.f);
    }
}
__global__ void k_zero_S() {
    int i = blockIdx.x * blockDim.x + threadIdx.x;
    if (i < NN * 32) ((float4*)g_S)[i] = make_float4(0.f, 0.f, 0.f, 0.f);
}

// ---------------------------------------------------------------------------
// Node encoder (scalar, R3): n = relu(x@W0+b0)@W1+b1
// ---------------------------------------------------------------------------
__global__ void k_node_enc(const float* __restrict__ x,
                           const float* __restrict__ W0, const float* __restrict__ b0,
                           const float* __restrict__ W1, const float* __restrict__ b1) {
    extern __shared__ float sm[];
    float* h_s = sm;                 // [64][132]
    float* B_s = sm + 64 * 132;      // [32][128]
    float* A_s = sm;                 // union, [64][33]

    const int tid = threadIdx.x;
    const int ty = tid >> 5, tx = tid & 31;
    const int m0 = ty * 8;
    const int j  = tx * 4;
    const int row0 = blockIdx.x * 64;

#pragma unroll
    for (int i = 0; i < 8; i++) {
        int idx = tid + i * 256;
        int m = idx >> 5, kk = idx & 31;
        int gr = row0 + m;
        A_s[m * 33 + kk] = (gr < NN) ? x[gr * 32 + kk] : 0.f;
    }
#pragma unroll
    for (int i = 0; i < 16; i++) B_s[tid + i * 256] = W0[tid + i * 256];
    __syncthreads();

    float acc[8][4];
    {
        float4 bv = *(const float4*)(b0 + j);
#pragma unroll
        for (int r = 0; r < 8; r++) { acc[r][0]=bv.x; acc[r][1]=bv.y; acc[r][2]=bv.z; acc[r][3]=bv.w; }
    }
    gemm_step<32, 33>(A_s, B_s, m0, j, acc);
    __syncthreads();

#pragma unroll
    for (int r = 0; r < 8; r++) {
        float4 h;
        h.x = fmaxf(acc[r][0], 0.f); h.y = fmaxf(acc[r][1], 0.f);
        h.z = fmaxf(acc[r][2], 0.f); h.w = fmaxf(acc[r][3], 0.f);
        *(float4*)(h_s + (m0 + r) * 132 + j) = h;
    }

    float o[8][4];
    {
        float4 bv = *(const float4*)(b1 + j);
#pragma unroll
        for (int r = 0; r < 8; r++) { o[r][0]=bv.x; o[r][1]=bv.y; o[r][2]=bv.z; o[r][3]=bv.w; }
    }
    for (int c = 0; c < 4; c++) {
        __syncthreads();
#pragma unroll
        for (int i = 0; i < 16; i++) B_s[tid + i * 256] = W1[c * 32 * 128 + tid + i * 256];
        __syncthreads();
        gemm_step<32, 132>(h_s + c * 32, B_s, m0, j, o);
    }
#pragma unroll
    for (int r = 0; r < 8; r++) {
        int gr = row0 + m0 + r;
        if (gr < NN)
            *(float4*)(g_n + gr * HDIM + j) = make_float4(o[r][0], o[r][1], o[r][2], o[r][3]);
    }
}

// ---------------------------------------------------------------------------
// Edge encoder + scatter (scalar, R3)
// ---------------------------------------------------------------------------
__global__ void __launch_bounds__(256) k_edge_enc_scatter(
        const float* __restrict__ x,
        const float* __restrict__ W0, const float* __restrict__ b0,
        const int* __restrict__ recvs) {
    __shared__ float A_s[64 * 17];
    __shared__ float B_s[16 * 128];
    __shared__ int   r_idx[64];

    const int tid = threadIdx.x;
    const int ty = tid >> 5, tx = tid & 31;
    const int m0 = ty * 8;
    const int j  = tx * 4;
    const int row0 = blockIdx.x * 64;

#pragma unroll
    for (int i = 0; i < 4; i++) {
        int idx = tid + i * 256;
        int m = idx >> 4, kk = idx & 15;
        A_s[m * 17 + kk] = x[(long)(row0 + m) * 16 + kk];
    }
#pragma unroll
    for (int i = 0; i < 8; i++) B_s[tid + i * 256] = W0[tid + i * 256];
    if (tid < 64) r_idx[tid] = recvs[row0 + tid];
    __syncthreads();

    float acc[8][4];
    {
        float4 bv = *(const float4*)(b0 + j);
#pragma unroll
        for (int r = 0; r < 8; r++) { acc[r][0]=bv.x; acc[r][1]=bv.y; acc[r][2]=bv.z; acc[r][3]=bv.w; }
    }
    gemm_step<16, 17>(A_s, B_s, m0, j, acc);

#pragma unroll
    for (int r = 0; r < 8; r++) {
        int rv = r_idx[m0 + r];
        float v0 = fmaxf(acc[r][0], 0.f), v1 = fmaxf(acc[r][1], 0.f);
        float v2 = fmaxf(acc[r][2], 0.f), v3 = fmaxf(acc[r][3], 0.f);
        float* dst = g_hsum + (long)rv * HDIM + j;
        asm volatile("red.global.add.v4.f32 [%0], {%1, %2, %3, %4};"
                     :: "l"(dst), "f"(v0), "f"(v1), "f"(v2), "f"(v3) : "memory");
        if (tx == 0) atomicAdd(g_deg + rv, 1.0f);
    }
}

// ---------------------------------------------------------------------------
// c_agg = g_hsum @ g_Wg + g_deg * g_bg  (scalar, R3)
// ---------------------------------------------------------------------------
__global__ void k_cagg() {
    extern __shared__ float sm[];
    float* A_s = sm;                 // [64][33]
    float* B_s = sm + 64 * 33;       // [32][128]

    const int tid = threadIdx.x;
    const int ty = tid >> 5, tx = tid & 31;
    const int m0 = ty * 8;
    const int j  = tx * 4;
    const int row0 = blockIdx.x * 64;

    float acc[8][4];
    {
        float4 bgv = *(const float4*)(g_bg + j);
#pragma unroll
        for (int r = 0; r < 8; r++) {
            int gr = row0 + m0 + r;
            float d = (gr < NN) ? g_deg[gr] : 0.f;
            acc[r][0] = d * bgv.x; acc[r][1] = d * bgv.y;
            acc[r][2] = d * bgv.z; acc[r][3] = d * bgv.w;
        }
    }
    for (int c = 0; c < 4; c++) {
        __syncthreads();
#pragma unroll
        for (int i = 0; i < 8; i++) {
            int idx = tid + i * 256;
            int m = idx >> 5, kk = idx & 31;
            int gr = row0 + m;
            A_s[m * 33 + kk] = (gr < NN) ? g_hsum[gr * HDIM + c * 32 + kk] : 0.f;
        }
#pragma unroll
        for (int i = 0; i < 16; i++) B_s[tid + i * 256] = g_Wg[c * 32 * 128 + tid + i * 256];
        __syncthreads();
        gemm_step<32, 33>(A_s, B_s, m0, j, acc);
    }
#pragma unroll
    for (int r = 0; r < 8; r++) {
        int gr = row0 + m0 + r;
        if (gr < NN)
            *(float4*)(g_cagg + gr * HDIM + j) =
                make_float4(acc[r][0], acc[r][1], acc[r][2], acc[r][3]);
    }
}

// ---------------------------------------------------------------------------
// Per-pass scatter: S[recv] += n[sender]
// ---------------------------------------------------------------------------
__global__ void __launch_bounds__(256) k_scatter_n(const int* __restrict__ senders,
                                                   const int* __restrict__ recvs) {
    const int e    = blockIdx.x * 8 + (threadIdx.x >> 5);
    const int lane = threadIdx.x & 31;
    const int j = lane * 4;
    const int s = __ldg(senders + e);
    const int r = __ldg(recvs + e);
    float4 v = *(const float4*)(g_n + (long)s * HDIM + j);
    float* dst = g_S + (long)r * HDIM + j;
    asm volatile("red.global.add.v4.f32 [%0], {%1, %2, %3, %4};"
                 :: "l"(dst), "f"(v.x), "f"(v.y), "f"(v.z), "f"(v.w) : "memory");
}

// ===========================================================================
// MMA node update. Block = 128 rows x 128 cols, 8 warps (16 rows each).
// Smem strides: A/B tiles 20 u32/row (80B, 16B-aligned, conflict-free);
// H tiles 68 u32/row.
// ===========================================================================
#define BST 20
#define U_AH 0
#define U_AL (U_AH + 128 * BST)
#define U_BH (U_AL + 128 * BST)
#define U_BL (U_BH + 128 * BST)
#define U_HH (U_BL + 128 * BST)
#define U_HL (U_HH + 128 * 68)
#define U_END (U_HL + 128 * 68)
#define SM_MMA (U_END * 4)          // 110592 bytes

// Vectorized A fill: 128 rows x 32 floats (chunk koff..koff+31), split bf16.
__device__ __forceinline__ void fillA(uint32* AhU, uint32* AlU,
                                      const float* __restrict__ src,
                                      int row0, int koff, int tid) {
#pragma unroll
    for (int i = 0; i < 4; i++) {
        int p = tid + i * 256;              // 1024 = 128 rows x 8 float4
        int row = p >> 3, q = p & 7;
        int gr = row0 + row;
        float4 v = make_float4(0.f, 0.f, 0.f, 0.f);
        if (gr < NN) v = *(const float4*)(src + (long)gr * HDIM + koff + 4 * q);
        float ex = __bfloat162float(__float2bfloat16_rn(v.x));
        float ey = __bfloat162float(__float2bfloat16_rn(v.y));
        float ez = __bfloat162float(__float2bfloat16_rn(v.z));
        float ew = __bfloat162float(__float2bfloat16_rn(v.w));
        uint2 hh = make_uint2(pack_bf2(v.x, v.y), pack_bf2(v.z, v.w));
        uint2 ll = make_uint2(pack_bf2(v.x - ex, v.y - ey), pack_bf2(v.z - ez, v.w - ew));
        *(uint2*)(AhU + row * BST + 2 * q) = hh;
        *(uint2*)(AlU + row * BST + 2 * q) = ll;
    }
}

// Vectorized B fill: 128 n-rows x 16 u32 (chunk), 128-bit ld/st.
__device__ __forceinline__ void fillB(uint32* BhU, uint32* BlU,
                                      const ushort16* __restrict__ gH,
                                      const ushort16* __restrict__ gL,
                                      int koff, int tid) {
    const uint4* sH = (const uint4*)gH;   // [n][16] uint4 per 128-k row
    const uint4* sL = (const uint4*)gL;
    int kq0 = koff >> 3;                  // quad offset within row
#pragma unroll
    for (int i = 0; i < 2; i++) {
        int p = tid + i * 256;            // 512 = 128 n x 4 quads
        int n = p >> 2, kq = p & 3;
        uint4 vh = sH[n * 16 + kq0 + kq];
        uint4 vl = sL[n * 16 + kq0 + kq];
        *(uint4*)(BhU + n * BST + 4 * kq) = vh;
        *(uint4*)(BlU + n * BST + 4 * kq) = vl;
    }
}

template<int AS>
__device__ __forceinline__ void mma_chunk(const uint32* AhU, const uint32* AlU,
                                          const uint32* BhU, const uint32* BlU,
                                          float acc[16][4], int rw0, int gid, int tg) {
#pragma unroll
    for (int kb2 = 0; kb2 <= 8; kb2 += 8) {
        int a0i = (rw0 + gid) * AS + kb2 + tg;
        int a1i = a0i + 8 * AS;
        uint32 ah0 = AhU[a0i],     ah1 = AhU[a1i];
        uint32 ah2 = AhU[a0i + 4], ah3 = AhU[a1i + 4];
        uint32 al0 = AlU[a0i],     al1 = AlU[a1i];
        uint32 al2 = AlU[a0i + 4], al3 = AlU[a1i + 4];
#pragma unroll
        for (int t = 0; t < 16; t++) {
            int bi = (8 * t + gid) * BST + kb2 + tg;
            uint32 bh0 = BhU[bi], bh1 = BhU[bi + 4];
            uint32 bl0 = BlU[bi], bl1 = BlU[bi + 4];
            MMA16816(acc[t], ah0, ah1, ah2, ah3, bh0, bh1);
            MMA16816(acc[t], ah0, ah1, ah2, ah3, bl0, bl1);
            MMA16816(acc[t], al0, al1, al2, al3, bh0, bh1);
        }
    }
}

__global__ void __launch_bounds__(256, 2) k_node_upd_mma(
        const float* __restrict__ b0, const float* __restrict__ b1,
        const float* __restrict__ lng, const float* __restrict__ lnb) {
    extern __shared__ uint32 smu[];
    uint32* AhU = smu + U_AH;
    uint32* AlU = smu + U_AL;
    uint32* BhU = smu + U_BH;
    uint32* BlU = smu + U_BL;
    uint32* HhU = smu + U_HH;
    uint32* HlU = smu + U_HL;

    const int tid = threadIdx.x;
    const int w = tid >> 5, lane = tid & 31;
    const int gid = lane >> 2, tg = lane & 3;
    const int rw0 = w * 16;
    const int row0 = blockIdx.x * 128;
    const int r_e = row0 + rw0 + gid;
    const int r_o = r_e + 8;

    float acc[16][4];

    // ---- hidden accumulator init: b0 + c_agg ----
#pragma unroll
    for (int t = 0; t < 16; t++) {
        int col = 8 * t + 2 * tg;
        float2 bb = *(const float2*)(b0 + col);
        float2 ce = (r_e < NN) ? *(const float2*)(g_cagg + (long)r_e * HDIM + col)
                               : make_float2(0.f, 0.f);
        float2 co = (r_o < NN) ? *(const float2*)(g_cagg + (long)r_o * HDIM + col)
                               : make_float2(0.f, 0.f);
        acc[t][0] = bb.x + ce.x; acc[t][1] = bb.y + ce.y;
        acc[t][2] = bb.x + co.x; acc[t][3] = bb.y + co.y;
    }

    // ---- hidden: K = 256 over [n | S] ----
    for (int c = 0; c < 8; c++) {
        const float* src = (c < 4) ? g_n : g_S;
        const ushort16* gH = (c < 4) ? g_BtopH : g_BWfH;
        const ushort16* gL = (c < 4) ? g_BtopL : g_BWfL;
        int koff = (c & 3) * 32;
        __syncthreads();
        fillA(AhU, AlU, src, row0, koff, tid);
        fillB(BhU, BlU, gH, gL, koff, tid);
        __syncthreads();
        mma_chunk<BST>(AhU, AlU, BhU, BlU, acc, rw0, gid, tg);
    }

    // ---- fused S zeroing for next pass (all S reads barrier-ordered above) ----
#pragma unroll
    for (int i = 0; i < 16; i++) {
        int p = tid + i * 256;              // 4096 = 128 rows x 32 float4
        int row = p >> 5, q = p & 31;
        int gr = row0 + row;
        if (gr < NN)
            ((float4*)(g_S + (long)gr * HDIM))[q] = make_float4(0.f, 0.f, 0.f, 0.f);
    }

    // ---- relu + split-store h to smem H ----
#pragma unroll
    for (int t = 0; t < 16; t++) {
        float h0 = fmaxf(acc[t][0], 0.f), h1 = fmaxf(acc[t][1], 0.f);
        float h2 = fmaxf(acc[t][2], 0.f), h3 = fmaxf(acc[t][3], 0.f);
        int ie = (rw0 + gid) * 68 + 4 * t + tg;
        int io = ie + 8 * 68;
        float e0 = __bfloat162float(__float2bfloat16_rn(h0));
        float e1 = __bfloat162float(__float2bfloat16_rn(h1));
        float e2 = __bfloat162float(__float2bfloat16_rn(h2));
        float e3 = __bfloat162float(__float2bfloat16_rn(h3));
        HhU[ie] = pack_bf2(h0, h1);
        HlU[ie] = pack_bf2(h0 - e0, h1 - e1);
        HhU[io] = pack_bf2(h2, h3);
        HlU[io] = pack_bf2(h2 - e2, h3 - e3);
    }

    // ---- residual: acc = n @ Wn ----
#pragma unroll
    for (int t = 0; t < 16; t++) {
        acc[t][0] = 0.f; acc[t][1] = 0.f; acc[t][2] = 0.f; acc[t][3] = 0.f;
    }
    for (int c = 0; c < 4; c++) {
        __syncthreads();
        fillA(AhU, AlU, g_n, row0, c * 32, tid);
        fillB(BhU, BlU, g_BresH, g_BresL, c * 32, tid);
        __syncthreads();
        mma_chunk<BST>(AhU, AlU, BhU, BlU, acc, rw0, gid, tg);
    }

    // ---- output: acc += h @ W1  (A from smem H) ----
    for (int c = 0; c < 4; c++) {
        __syncthreads();
        fillB(BhU, BlU, g_BoutH, g_BoutL, c * 32, tid);
        __syncthreads();
        mma_chunk<68>(HhU + 16 * c, HlU + 16 * c, BhU, BlU, acc, rw0, gid, tg);
    }

    // ---- + b1, LayerNorm (warp-local rows), write g_n ----
    float s1e = 0.f, s2e = 0.f, s1o = 0.f, s2o = 0.f;
#pragma unroll
    for (int t = 0; t < 16; t++) {
        int col = 8 * t + 2 * tg;
        float2 bb = *(const float2*)(b1 + col);
        acc[t][0] += bb.x; acc[t][1] += bb.y;
        acc[t][2] += bb.x; acc[t][3] += bb.y;
        s1e += acc[t][0] + acc[t][1];
        s2e += acc[t][0] * acc[t][0] + acc[t][1] * acc[t][1];
        s1o += acc[t][2] + acc[t][3];
        s2o += acc[t][2] * acc[t][2] + acc[t][3] * acc[t][3];
    }
#pragma unroll
    for (int off = 1; off <= 2; off <<= 1) {
        s1e += __shfl_xor_sync(0xffffffffu, s1e, off);
        s2e += __shfl_xor_sync(0xffffffffu, s2e, off);
        s1o += __shfl_xor_sync(0xffffffffu, s1o, off);
        s2o += __shfl_xor_sync(0xffffffffu, s2o, off);
    }
    float mu_e = s1e * (1.f / 128.f);
    float mu_o = s1o * (1.f / 128.f);
    float inv_e = rsqrtf(s2e * (1.f / 128.f) - mu_e * mu_e + LN_EPS);
    float inv_o = rsqrtf(s2o * (1.f / 128.f) - mu_o * mu_o + LN_EPS);

#pragma unroll
    for (int t = 0; t < 16; t++) {
        int col = 8 * t + 2 * tg;
        float2 gv = *(const float2*)(lng + col);
        float2 bv = *(const float2*)(lnb + col);
        if (r_e < NN) {
            float2 o;
            o.x = (acc[t][0] - mu_e) * inv_e * gv.x + bv.x;
            o.y = (acc[t][1] - mu_e) * inv_e * gv.y + bv.y;
            *(float2*)(g_n + (long)r_e * HDIM + col) = o;
        }
        if (r_o < NN) {
            float2 o;
            o.x = (acc[t][2] - mu_o) * inv_o * gv.x + bv.x;
            o.y = (acc[t][3] - mu_o) * inv_o * gv.y + bv.y;
            *(float2*)(g_n + (long)r_o * HDIM + col) = o;
        }
    }
}

// ---------------------------------------------------------------------------
// Decoder (scalar, R3): out = relu(n @ W0 + b0) @ W1 + b1
// ---------------------------------------------------------------------------
__global__ void k_dec(const float* __restrict__ W0, const float* __restrict__ b0,
                      const float* __restrict__ W1, const float* __restrict__ b1,
                      float* __restrict__ out) {
    extern __shared__ float sm[];
    float* h_s  = sm;                 // [64][132]
    float* B_s  = sm + 64 * 132;      // [32][128]
    float* A_s  = sm;                 // union, [64][33]
    float* w1_s = B_s + 32 * 128;     // [256]
    float* b1_s = w1_s + 256;         // [2]

    const int tid = threadIdx.x;
    const int ty = tid >> 5, tx = tid & 31;
    const int m0 = ty * 8;
    const int j  = tx * 4;
    const int row0 = blockIdx.x * 64;

    float acc[8][4];
    {
        float4 bv = *(const float4*)(b0 + j);
#pragma unroll
        for (int r = 0; r < 8; r++) { acc[r][0]=bv.x; acc[r][1]=bv.y; acc[r][2]=bv.z; acc[r][3]=bv.w; }
    }
    for (int c = 0; c < 4; c++) {
        __syncthreads();
#pragma unroll
        for (int i = 0; i < 8; i++) {
            int idx = tid + i * 256;
            int m = idx >> 5, kk = idx & 31;
            int gr = row0 + m;
            A_s[m * 33 + kk] = (gr < NN) ? g_n[gr * HDIM + c * 32 + kk] : 0.f;
        }
#pragma unroll
        for (int i = 0; i < 16; i++) B_s[tid + i * 256] = W0[c * 32 * 128 + tid + i * 256];
        __syncthreads();
        gemm_step<32, 33>(A_s, B_s, m0, j, acc);
    }
    __syncthreads();
#pragma unroll
    for (int r = 0; r < 8; r++) {
        float4 h;
        h.x = fmaxf(acc[r][0], 0.f); h.y = fmaxf(acc[r][1], 0.f);
        h.z = fmaxf(acc[r][2], 0.f); h.w = fmaxf(acc[r][3], 0.f);
        *(float4*)(h_s + (m0 + r) * 132 + j) = h;
    }
    w1_s[tid] = W1[tid];
    if (tid < 2) b1_s[tid] = b1[tid];
    __syncthreads();

    if (tid < 128) {
        int row = tid >> 1, c = tid & 1;
        float s = b1_s[c];
#pragma unroll 8
        for (int k = 0; k < 128; k++)
            s = fmaf(h_s[row * 132 + k], w1_s[k * 2 + c], s);
        int gr = row0 + row;
        if (gr < NN) out[gr * 2 + c] = s;
    }
}

// ---------------------------------------------------------------------------
extern "C" void kernel_launch(void* const* d_in, const int* in_sizes, int n_in,
                              void* d_out, int out_size) {
    const float* nodes   = (const float*)d_in[0];
    const float* edges   = (const float*)d_in[1];
    const int*   senders = (const int*)  d_in[2];
    const int*   recvs   = (const int*)  d_in[3];
    const float* enW0 = (const float*)d_in[4];
    const float* enb0 = (const float*)d_in[5];
    const float* enW1 = (const float*)d_in[6];
    const float* enb1 = (const float*)d_in[7];
    const float* eeW0 = (const float*)d_in[8];
    const float* eeb0 = (const float*)d_in[9];
    const float* eeW1 = (const float*)d_in[10];
    const float* eeb1 = (const float*)d_in[11];
    const float* Wmsg = (const float*)d_in[12];
    const float* nW0  = (const float*)d_in[13];
    const float* nb0  = (const float*)d_in[14];
    const float* nW1  = (const float*)d_in[15];
    const float* nb1  = (const float*)d_in[16];
    const float* Wnode= (const float*)d_in[17];
    const float* lng  = (const float*)d_in[18];
    const float* lnb  = (const float*)d_in[19];
    const float* dW0  = (const float*)d_in[20];
    const float* db0  = (const float*)d_in[21];
    const float* dW1  = (const float*)d_in[22];
    const float* db1  = (const float*)d_in[23];
    float* out = (float*)d_out;

    const int SM_BIG  = (64 * 132 + 32 * 128) * 4;              // 50176
    const int SM_MSG  = (64 * 33 + 32 * 128) * 4;               // 24832
    const int SM_DEC  = (64 * 132 + 32 * 128 + 256 + 2) * 4;    // 51208

    cudaFuncSetAttribute(k_node_enc,     cudaFuncAttributeMaxDynamicSharedMemorySize, SM_BIG);
    cudaFuncSetAttribute(k_cagg,         cudaFuncAttributeMaxDynamicSharedMemorySize, SM_MSG);
    cudaFuncSetAttribute(k_node_upd_mma, cudaFuncAttributeMaxDynamicSharedMemorySize, SM_MMA);
    cudaFuncSetAttribute(k_dec,          cudaFuncAttributeMaxDynamicSharedMemorySize, SM_DEC);

    // Folds, splits, invariants
    k_fold1<<<129, 128>>>(eeW1, eeb1, Wmsg);
    k_fold2<<<257, 128>>>(nW0, Wmsg);
    k_splitB<<<64, 256>>>(nW0,   0);   // W0 top half -> g_Btop
    k_splitB<<<64, 256>>>(Wnode, 1);   // -> g_Bres
    k_splitB<<<64, 256>>>(nW1,   2);   // -> g_Bout
    k_zero_pre<<<(NN * 32 + NN / 4 + 255) / 256, 256>>>();
    k_zero_S<<<(NN * 32 + 255) / 256, 256>>>();   // once; upd re-zeroes per pass
    k_node_enc<<<NODE_TILES, 256, SM_BIG>>>(nodes, enW0, enb0, enW1, enb1);
    k_edge_enc_scatter<<<EDGE_TILES, 256>>>(edges, eeW0, eeb0, recvs);
    k_cagg<<<NODE_TILES, 256, SM_MSG>>>();

    for (int p = 0; p < NPASS; p++) {
        k_scatter_n<<<NEDGE / 8, 256>>>(senders, recvs);
        k_node_upd_mma<<<NT128, 256, SM_MMA>>>(nb0, nb1, lng, lnb);
    }

    k_dec<<<NODE_TILES, 256, SM_DEC>>>(dW0, db0, dW1, db1, out);
}

// round 9
// speedup vs baseline: 1.8797x; 1.0284x over previous
#include <cuda_runtime.h>
#include <cuda_bf16.h>
#include <math.h>

#define NN     50000
#define NEDGE  600000
#define HDIM   128
#define NPASS  5
#define LN_EPS 1e-6f

#define NODE_TILES ((NN + 63) / 64)     // 782  (scalar kernels)
#define NT128      ((NN + 127) / 128)   // 391  (mma node_upd)
#define EDGE_TILES (NEDGE / 64)         // 9375

typedef unsigned int uint32;
typedef unsigned short ushort16;

// Persistent device scratch — double-buffered node features
__device__ float g_n0[NN * HDIM];
__device__ float g_n1[NN * HDIM];
__device__ float g_hsum[NN * HDIM];
__device__ float g_cagg[NN * HDIM];
__device__ float g_T1[HDIM * HDIM];     // W1e @ Wm_bot
__device__ float g_tvec[HDIM];          // b1e @ Wm_bot
__device__ float g_Wg[HDIM * HDIM];     // (W1e @ Wm_bot) @ W0_bot
__device__ float g_bg[HDIM];

// Receiver-CSR of the edge list (built once per launch)
__device__ int g_rowptr[NN + 1];
__device__ int g_cursor[NN];
__device__ int g_col[NEDGE];

// Split-bf16 weight tables, [N][K] k-contiguous (transposed)
__device__ __align__(16) ushort16 g_BtopH[HDIM * HDIM], g_BtopL[HDIM * HDIM]; // W0_top
__device__ __align__(16) ushort16 g_BWfH [HDIM * HDIM], g_BWfL [HDIM * HDIM]; // Wm_top@W0_bot
__device__ __align__(16) ushort16 g_BresH[HDIM * HDIM], g_BresL[HDIM * HDIM]; // Wn
__device__ __align__(16) ushort16 g_BoutH[HDIM * HDIM], g_BoutL[HDIM * HDIM]; // W1

// ---------------------------------------------------------------------------
// Scalar register-tiled GEMM micro-step — used by enc/cagg/dec
// ---------------------------------------------------------------------------
template<int KC, int LDA>
__device__ __forceinline__ void gemm_step(const float* __restrict__ A_s,
                                          const float* __restrict__ B_s,
                                          int m0, int j, float acc[8][4]) {
#pragma unroll 8
    for (int kk = 0; kk < KC; kk++) {
        float4 b = *(const float4*)(B_s + kk * HDIM + j);
#pragma unroll
        for (int r = 0; r < 8; r++) {
            float a = A_s[(m0 + r) * LDA + kk];
            acc[r][0] = fmaf(a, b.x, acc[r][0]);
            acc[r][1] = fmaf(a, b.y, acc[r][1]);
            acc[r][2] = fmaf(a, b.z, acc[r][2]);
            acc[r][3] = fmaf(a, b.w, acc[r][3]);
        }
    }
}

// ---------------------------------------------------------------------------
// bf16 helpers + MMA
// ---------------------------------------------------------------------------
__device__ __forceinline__ uint32 pack_bf2(float x, float y) {
    __nv_bfloat162 t = __floats2bfloat162_rn(x, y);
    return *reinterpret_cast<uint32*>(&t);
}
__device__ __forceinline__ void split_bf(float v, ushort16& h, ushort16& l) {
    __nv_bfloat16 hb = __float2bfloat16_rn(v);
    float lo = v - __bfloat162float(hb);
    __nv_bfloat16 lb = __float2bfloat16_rn(lo);
    h = *reinterpret_cast<ushort16*>(&hb);
    l = *reinterpret_cast<ushort16*>(&lb);
}
#define MMA16816(d, a0,a1,a2,a3, b0,b1) \
    asm volatile("mma.sync.aligned.m16n8k16.row.col.f32.bf16.bf16.f32 " \
        "{%0,%1,%2,%3},{%4,%5,%6,%7},{%8,%9},{%0,%1,%2,%3};" \
        : "+f"((d)[0]), "+f"((d)[1]), "+f"((d)[2]), "+f"((d)[3]) \
        : "r"(a0), "r"(a1), "r"(a2), "r"(a3), "r"(b0), "r"(b1))

// ---------------------------------------------------------------------------
// Weight folds
// ---------------------------------------------------------------------------
__global__ void k_fold1(const float* __restrict__ W1e, const float* __restrict__ b1e,
                        const float* __restrict__ Wm) {
    __shared__ float a[HDIM];
    int j = threadIdx.x;
    a[j] = (blockIdx.x < 128) ? W1e[blockIdx.x * HDIM + j] : b1e[j];
    __syncthreads();
    float s = 0.f;
#pragma unroll 8
    for (int l = 0; l < HDIM; l++)
        s = fmaf(a[l], Wm[(HDIM + l) * HDIM + j], s);
    if (blockIdx.x < 128) g_T1[blockIdx.x * HDIM + j] = s;
    else                  g_tvec[j] = s;
}

__global__ void k_fold2(const float* __restrict__ W0n, const float* __restrict__ Wm) {
    __shared__ float a[HDIM];
    int j = threadIdx.x;
    int bid = blockIdx.x;
    if (bid < 128)       a[j] = g_T1[bid * HDIM + j];
    else if (bid == 128) a[j] = g_tvec[j];
    else                 a[j] = Wm[(bid - 129) * HDIM + j];
    __syncthreads();
    float s = 0.f;
#pragma unroll 8
    for (int l = 0; l < HDIM; l++)
        s = fmaf(a[l], W0n[(HDIM + l) * HDIM + j], s);
    if (bid < 128)       g_Wg[bid * HDIM + j] = s;
    else if (bid == 128) g_bg[j] = s;
    else {
        int k = bid - 129;
        ushort16 h, l2; split_bf(s, h, l2);
        g_BWfH[j * HDIM + k] = h;
        g_BWfL[j * HDIM + k] = l2;
    }
}

// Split + transpose a [128][128] fp32 weight into [N][K] bf16 hi/lo.
// `which` selects the destination table IN DEVICE CODE (R6 lesson).
__global__ void k_splitB(const float* __restrict__ W, int which) {
    ushort16* dH; ushort16* dL;
    if (which == 0)      { dH = g_BtopH; dL = g_BtopL; }
    else if (which == 1) { dH = g_BresH; dL = g_BresL; }
    else                 { dH = g_BoutH; dL = g_BoutL; }
    int idx = blockIdx.x * 256 + threadIdx.x;
    int k = idx >> 7, n = idx & 127;
    ushort16 h, l;
    split_bf(W[k * HDIM + n], h, l);
    dH[n * HDIM + k] = h;
    dL[n * HDIM + k] = l;
}

// ---------------------------------------------------------------------------
// CSR build + zero helpers
// ---------------------------------------------------------------------------
__global__ void k_zero_pre() {   // zero g_hsum (float4) and g_cursor (int4)
    int i = blockIdx.x * blockDim.x + threadIdx.x;
    if (i < NN * 32) ((float4*)g_hsum)[i] = make_float4(0.f, 0.f, 0.f, 0.f);
    else {
        int d = i - NN * 32;
        if (d < NN / 4) ((int4*)g_cursor)[d] = make_int4(0, 0, 0, 0);
    }
}

__global__ void k_hist(const int* __restrict__ recvs) {
    int e = blockIdx.x * 256 + threadIdx.x;
    if (e < NEDGE) atomicAdd(g_cursor + recvs[e], 1);
}

// Single-block exclusive scan over 50K counts -> rowptr; cursor := rowptr
__global__ void __launch_bounds__(1024) k_scan() {
    __shared__ int partial[1024];
    const int CHUNK = (NN + 1023) / 1024;   // 49
    int t = threadIdx.x;
    int beg = t * CHUNK, end = min(beg + CHUNK, NN);
    int s = 0;
    for (int i = beg; i < end; i++) s += g_cursor[i];
    partial[t] = s;
    __syncthreads();
    for (int off = 1; off < 1024; off <<= 1) {
        int v = (t >= off) ? partial[t - off] : 0;
        __syncthreads();
        partial[t] += v;
        __syncthreads();
    }
    int base = (t > 0) ? partial[t - 1] : 0;
    for (int i = beg; i < end; i++) {
        int c = g_cursor[i];
        g_rowptr[i] = base;
        g_cursor[i] = base;
        base += c;
    }
    if (t == 1023) g_rowptr[NN] = partial[1023];
}

__global__ void k_fillcsr(const int* __restrict__ senders,
                          const int* __restrict__ recvs) {
    int e = blockIdx.x * 256 + threadIdx.x;
    if (e < NEDGE) {
        int pos = atomicAdd(g_cursor + recvs[e], 1);
        g_col[pos] = senders[e];
    }
}

// ---------------------------------------------------------------------------
// Node encoder (scalar): n0 = relu(x@W0+b0)@W1+b1
// ---------------------------------------------------------------------------
__global__ void k_node_enc(const float* __restrict__ x,
                           const float* __restrict__ W0, const float* __restrict__ b0,
                           const float* __restrict__ W1, const float* __restrict__ b1) {
    extern __shared__ float sm[];
    float* h_s = sm;                 // [64][132]
    float* B_s = sm + 64 * 132;      // [32][128]
    float* A_s = sm;                 // union, [64][33]

    const int tid = threadIdx.x;
    const int ty = tid >> 5, tx = tid & 31;
    const int m0 = ty * 8;
    const int j  = tx * 4;
    const int row0 = blockIdx.x * 64;

#pragma unroll
    for (int i = 0; i < 8; i++) {
        int idx = tid + i * 256;
        int m = idx >> 5, kk = idx & 31;
        int gr = row0 + m;
        A_s[m * 33 + kk] = (gr < NN) ? x[gr * 32 + kk] : 0.f;
    }
#pragma unroll
    for (int i = 0; i < 16; i++) B_s[tid + i * 256] = W0[tid + i * 256];
    __syncthreads();

    float acc[8][4];
    {
        float4 bv = *(const float4*)(b0 + j);
#pragma unroll
        for (int r = 0; r < 8; r++) { acc[r][0]=bv.x; acc[r][1]=bv.y; acc[r][2]=bv.z; acc[r][3]=bv.w; }
    }
    gemm_step<32, 33>(A_s, B_s, m0, j, acc);
    __syncthreads();

#pragma unroll
    for (int r = 0; r < 8; r++) {
        float4 h;
        h.x = fmaxf(acc[r][0], 0.f); h.y = fmaxf(acc[r][1], 0.f);
        h.z = fmaxf(acc[r][2], 0.f); h.w = fmaxf(acc[r][3], 0.f);
        *(float4*)(h_s + (m0 + r) * 132 + j) = h;
    }

    float o[8][4];
    {
        float4 bv = *(const float4*)(b1 + j);
#pragma unroll
        for (int r = 0; r < 8; r++) { o[r][0]=bv.x; o[r][1]=bv.y; o[r][2]=bv.z; o[r][3]=bv.w; }
    }
    for (int c = 0; c < 4; c++) {
        __syncthreads();
#pragma unroll
        for (int i = 0; i < 16; i++) B_s[tid + i * 256] = W1[c * 32 * 128 + tid + i * 256];
        __syncthreads();
        gemm_step<32, 132>(h_s + c * 32, B_s, m0, j, o);
    }
#pragma unroll
    for (int r = 0; r < 8; r++) {
        int gr = row0 + m0 + r;
        if (gr < NN)
            *(float4*)(g_n0 + gr * HDIM + j) = make_float4(o[r][0], o[r][1], o[r][2], o[r][3]);
    }
}

// ---------------------------------------------------------------------------
// Edge encoder + scatter: h = relu(x@W0+b0); g_hsum[recv] += h
// ---------------------------------------------------------------------------
__global__ void __launch_bounds__(256) k_edge_enc_scatter(
        const float* __restrict__ x,
        const float* __restrict__ W0, const float* __restrict__ b0,
        const int* __restrict__ recvs) {
    __shared__ float A_s[64 * 17];
    __shared__ float B_s[16 * 128];
    __shared__ int   r_idx[64];

    const int tid = threadIdx.x;
    const int ty = tid >> 5, tx = tid & 31;
    const int m0 = ty * 8;
    const int j  = tx * 4;
    const int row0 = blockIdx.x * 64;

#pragma unroll
    for (int i = 0; i < 4; i++) {
        int idx = tid + i * 256;
        int m = idx >> 4, kk = idx & 15;
        A_s[m * 17 + kk] = x[(long)(row0 + m) * 16 + kk];
    }
#pragma unroll
    for (int i = 0; i < 8; i++) B_s[tid + i * 256] = W0[tid + i * 256];
    if (tid < 64) r_idx[tid] = recvs[row0 + tid];
    __syncthreads();

    float acc[8][4];
    {
        float4 bv = *(const float4*)(b0 + j);
#pragma unroll
        for (int r = 0; r < 8; r++) { acc[r][0]=bv.x; acc[r][1]=bv.y; acc[r][2]=bv.z; acc[r][3]=bv.w; }
    }
    gemm_step<16, 17>(A_s, B_s, m0, j, acc);

#pragma unroll
    for (int r = 0; r < 8; r++) {
        int rv = r_idx[m0 + r];
        float v0 = fmaxf(acc[r][0], 0.f), v1 = fmaxf(acc[r][1], 0.f);
        float v2 = fmaxf(acc[r][2], 0.f), v3 = fmaxf(acc[r][3], 0.f);
        float* dst = g_hsum + (long)rv * HDIM + j;
        asm volatile("red.global.add.v4.f32 [%0], {%1, %2, %3, %4};"
                     :: "l"(dst), "f"(v0), "f"(v1), "f"(v2), "f"(v3) : "memory");
    }
}

// ---------------------------------------------------------------------------
// c_agg = g_hsum @ g_Wg + deg * g_bg   (deg from rowptr diffs)
// ---------------------------------------------------------------------------
__global__ void k_cagg() {
    extern __shared__ float sm[];
    float* A_s = sm;                 // [64][33]
    float* B_s = sm + 64 * 33;       // [32][128]

    const int tid = threadIdx.x;
    const int ty = tid >> 5, tx = tid & 31;
    const int m0 = ty * 8;
    const int j  = tx * 4;
    const int row0 = blockIdx.x * 64;

    float acc[8][4];
    {
        float4 bgv = *(const float4*)(g_bg + j);
#pragma unroll
        for (int r = 0; r < 8; r++) {
            int gr = row0 + m0 + r;
            float d = (gr < NN) ? (float)(g_rowptr[gr + 1] - g_rowptr[gr]) : 0.f;
            acc[r][0] = d * bgv.x; acc[r][1] = d * bgv.y;
            acc[r][2] = d * bgv.z; acc[r][3] = d * bgv.w;
        }
    }
    for (int c = 0; c < 4; c++) {
        __syncthreads();
#pragma unroll
        for (int i = 0; i < 8; i++) {
            int idx = tid + i * 256;
            int m = idx >> 5, kk = idx & 31;
            int gr = row0 + m;
            A_s[m * 33 + kk] = (gr < NN) ? g_hsum[gr * HDIM + c * 32 + kk] : 0.f;
        }
#pragma unroll
        for (int i = 0; i < 16; i++) B_s[tid + i * 256] = g_Wg[c * 32 * 128 + tid + i * 256];
        __syncthreads();
        gemm_step<32, 33>(A_s, B_s, m0, j, acc);
    }
#pragma unroll
    for (int r = 0; r < 8; r++) {
        int gr = row0 + m0 + r;
        if (gr < NN)
            *(float4*)(g_cagg + gr * HDIM + j) =
                make_float4(acc[r][0], acc[r][1], acc[r][2], acc[r][3]);
    }
}

// ===========================================================================
// Fused MMA node update: CSR-gather S into smem H (split bf16) -> hidden
// (K=256: n chunks from gmem, S chunks from H) -> relu h into H -> residual
// -> output -> LayerNorm -> write OTHER n buffer (double-buffered).
// ===========================================================================
#define BST 20
#define U_AH 0
#define U_AL (U_AH + 128 * BST)
#define U_BH (U_AL + 128 * BST)
#define U_BL (U_BH + 128 * BST)
#define U_HH (U_BL + 128 * BST)
#define U_HL (U_HH + 128 * 68)
#define U_END (U_HL + 128 * 68)
#define SM_MMA (U_END * 4)          // 110592 bytes

__device__ __forceinline__ void fillA(uint32* AhU, uint32* AlU,
                                      const float* __restrict__ src,
                                      int row0, int koff, int tid) {
#pragma unroll
    for (int i = 0; i < 4; i++) {
        int p = tid + i * 256;
        int row = p >> 3, q = p & 7;
        int gr = row0 + row;
        float4 v = make_float4(0.f, 0.f, 0.f, 0.f);
        if (gr < NN) v = *(const float4*)(src + (long)gr * HDIM + koff + 4 * q);
        float ex = __bfloat162float(__float2bfloat16_rn(v.x));
        float ey = __bfloat162float(__float2bfloat16_rn(v.y));
        float ez = __bfloat162float(__float2bfloat16_rn(v.z));
        float ew = __bfloat162float(__float2bfloat16_rn(v.w));
        uint2 hh = make_uint2(pack_bf2(v.x, v.y), pack_bf2(v.z, v.w));
        uint2 ll = make_uint2(pack_bf2(v.x - ex, v.y - ey), pack_bf2(v.z - ez, v.w - ew));
        *(uint2*)(AhU + row * BST + 2 * q) = hh;
        *(uint2*)(AlU + row * BST + 2 * q) = ll;
    }
}

__device__ __forceinline__ void fillB(uint32* BhU, uint32* BlU,
                                      const ushort16* __restrict__ gH,
                                      const ushort16* __restrict__ gL,
                                      int koff, int tid) {
    const uint4* sH = (const uint4*)gH;
    const uint4* sL = (const uint4*)gL;
    int kq0 = koff >> 3;
#pragma unroll
    for (int i = 0; i < 2; i++) {
        int p = tid + i * 256;
        int n = p >> 2, kq = p & 3;
        uint4 vh = sH[n * 16 + kq0 + kq];
        uint4 vl = sL[n * 16 + kq0 + kq];
        *(uint4*)(BhU + n * BST + 4 * kq) = vh;
        *(uint4*)(BlU + n * BST + 4 * kq) = vl;
    }
}

template<int AS>
__device__ __forceinline__ void mma_chunk(const uint32* AhU, const uint32* AlU,
                                          const uint32* BhU, const uint32* BlU,
                                          float acc[16][4], int rw0, int gid, int tg) {
#pragma unroll
    for (int kb2 = 0; kb2 <= 8; kb2 += 8) {
        int a0i = (rw0 + gid) * AS + kb2 + tg;
        int a1i = a0i + 8 * AS;
        uint32 ah0 = AhU[a0i],     ah1 = AhU[a1i];
        uint32 ah2 = AhU[a0i + 4], ah3 = AhU[a1i + 4];
        uint32 al0 = AlU[a0i],     al1 = AlU[a1i];
        uint32 al2 = AlU[a0i + 4], al3 = AlU[a1i + 4];
#pragma unroll
        for (int t = 0; t < 16; t++) {
            int bi = (8 * t + gid) * BST + kb2 + tg;
            uint32 bh0 = BhU[bi], bh1 = BhU[bi + 4];
            uint32 bl0 = BlU[bi], bl1 = BlU[bi + 4];
            MMA16816(acc[t], ah0, ah1, ah2, ah3, bh0, bh1);
            MMA16816(acc[t], ah0, ah1, ah2, ah3, bl0, bl1);
            MMA16816(acc[t], al0, al1, al2, al3, bh0, bh1);
        }
    }
}

__global__ void __launch_bounds__(256, 2) k_node_upd_mma(
        const float* __restrict__ b0, const float* __restrict__ b1,
        const float* __restrict__ lng, const float* __restrict__ lnb,
        int par) {
    extern __shared__ uint32 smu[];
    uint32* AhU = smu + U_AH;
    uint32* AlU = smu + U_AL;
    uint32* BhU = smu + U_BH;
    uint32* BlU = smu + U_BL;
    uint32* HhU = smu + U_HH;
    uint32* HlU = smu + U_HL;

    const float* ncur = (par == 0) ? g_n0 : g_n1;   // device-side select
    float*       nnxt = (par == 0) ? g_n1 : g_n0;

    const int tid = threadIdx.x;
    const int w = tid >> 5, lane = tid & 31;
    const int gid = lane >> 2, tg = lane & 3;
    const int rw0 = w * 16;
    const int row0 = blockIdx.x * 128;
    const int r_e = row0 + rw0 + gid;
    const int r_o = r_e + 8;
    const int jj = lane * 4;                         // gather column (4 floats)

    // ---- CSR gather: S rows for this tile -> H buffers (split bf16) ----
    for (int rr = 0; rr < 16; rr++) {
        int row = rw0 + rr;
        int gr = row0 + row;
        float a0 = 0.f, a1 = 0.f, a2 = 0.f, a3 = 0.f;
        if (gr < NN) {
            int e   = g_rowptr[gr];
            int end = g_rowptr[gr + 1];
            for (; e + 4 <= end; e += 4) {
                int s0 = g_col[e],     s1 = g_col[e + 1];
                int s2 = g_col[e + 2], s3 = g_col[e + 3];
                float4 v0 = *(const float4*)(ncur + (long)s0 * HDIM + jj);
                float4 v1 = *(const float4*)(ncur + (long)s1 * HDIM + jj);
                float4 v2 = *(const float4*)(ncur + (long)s2 * HDIM + jj);
                float4 v3 = *(const float4*)(ncur + (long)s3 * HDIM + jj);
                a0 += v0.x + v1.x + v2.x + v3.x;
                a1 += v0.y + v1.y + v2.y + v3.y;
                a2 += v0.z + v1.z + v2.z + v3.z;
                a3 += v0.w + v1.w + v2.w + v3.w;
            }
            for (; e < end; e++) {
                int s = g_col[e];
                float4 v = *(const float4*)(ncur + (long)s * HDIM + jj);
                a0 += v.x; a1 += v.y; a2 += v.z; a3 += v.w;
            }
        }
        float e0 = __bfloat162float(__float2bfloat16_rn(a0));
        float e1 = __bfloat162float(__float2bfloat16_rn(a1));
        float e2 = __bfloat162float(__float2bfloat16_rn(a2));
        float e3 = __bfloat162float(__float2bfloat16_rn(a3));
        uint2 hh = make_uint2(pack_bf2(a0, a1), pack_bf2(a2, a3));
        uint2 ll = make_uint2(pack_bf2(a0 - e0, a1 - e1), pack_bf2(a2 - e2, a3 - e3));
        *(uint2*)(HhU + row * 68 + lane * 2) = hh;
        *(uint2*)(HlU + row * 68 + lane * 2) = ll;
    }

    float acc[16][4];

    // ---- hidden accumulator init: b0 + c_agg ----
#pragma unroll
    for (int t = 0; t < 16; t++) {
        int col = 8 * t + 2 * tg;
        float2 bb = *(const float2*)(b0 + col);
        float2 ce = (r_e < NN) ? *(const float2*)(g_cagg + (long)r_e * HDIM + col)
                               : make_float2(0.f, 0.f);
        float2 co = (r_o < NN) ? *(const float2*)(g_cagg + (long)r_o * HDIM + col)
                               : make_float2(0.f, 0.f);
        acc[t][0] = bb.x + ce.x; acc[t][1] = bb.y + ce.y;
        acc[t][2] = bb.x + co.x; acc[t][3] = bb.y + co.y;
    }

    // ---- hidden: K = 256 — n chunks (c<4) from gmem, S chunks (c>=4) from H ----
    for (int c = 0; c < 8; c++) {
        int koff = (c & 3) * 32;
        __syncthreads();
        if (c < 4) fillA(AhU, AlU, ncur, row0, koff, tid);
        fillB(BhU, BlU, (c < 4) ? g_BtopH : g_BWfH,
                        (c < 4) ? g_BtopL : g_BWfL, koff, tid);
        __syncthreads();
        if (c < 4) mma_chunk<BST>(AhU, AlU, BhU, BlU, acc, rw0, gid, tg);
        else       mma_chunk<68>(HhU + 16 * (c - 4), HlU + 16 * (c - 4),
                                 BhU, BlU, acc, rw0, gid, tg);
    }

    // ---- relu + split-store h to smem H (S no longer needed) ----
    __syncthreads();
#pragma unroll
    for (int t = 0; t < 16; t++) {
        float h0 = fmaxf(acc[t][0], 0.f), h1 = fmaxf(acc[t][1], 0.f);
        float h2 = fmaxf(acc[t][2], 0.f), h3 = fmaxf(acc[t][3], 0.f);
        int ie = (rw0 + gid) * 68 + 4 * t + tg;
        int io = ie + 8 * 68;
        float e0 = __bfloat162float(__float2bfloat16_rn(h0));
        float e1 = __bfloat162float(__float2bfloat16_rn(h1));
        float e2 = __bfloat162float(__float2bfloat16_rn(h2));
        float e3 = __bfloat162float(__float2bfloat16_rn(h3));
        HhU[ie] = pack_bf2(h0, h1);
        HlU[ie] = pack_bf2(h0 - e0, h1 - e1);
        HhU[io] = pack_bf2(h2, h3);
        HlU[io] = pack_bf2(h2 - e2, h3 - e3);
    }

    // ---- residual: acc = n @ Wn ----
#pragma unroll
    for (int t = 0; t < 16; t++) {
        acc[t][0] = 0.f; acc[t][1] = 0.f; acc[t][2] = 0.f; acc[t][3] = 0.f;
    }
    for (int c = 0; c < 4; c++) {
        __syncthreads();
        fillA(AhU, AlU, ncur, row0, c * 32, tid);
        fillB(BhU, BlU, g_BresH, g_BresL, c * 32, tid);
        __syncthreads();
        mma_chunk<BST>(AhU, AlU, BhU, BlU, acc, rw0, gid, tg);
    }

    // ---- output: acc += h @ W1  (A from smem H) ----
    for (int c = 0; c < 4; c++) {
        __syncthreads();
        fillB(BhU, BlU, g_BoutH, g_BoutL, c * 32, tid);
        __syncthreads();
        mma_chunk<68>(HhU + 16 * c, HlU + 16 * c, BhU, BlU, acc, rw0, gid, tg);
    }

    // ---- + b1, LayerNorm (warp-local rows), write OTHER buffer ----
    float s1e = 0.f, s2e = 0.f, s1o = 0.f, s2o = 0.f;
#pragma unroll
    for (int t = 0; t < 16; t++) {
        int col = 8 * t + 2 * tg;
        float2 bb = *(const float2*)(b1 + col);
        acc[t][0] += bb.x; acc[t][1] += bb.y;
        acc[t][2] += bb.x; acc[t][3] += bb.y;
        s1e += acc[t][0] + acc[t][1];
        s2e += acc[t][0] * acc[t][0] + acc[t][1] * acc[t][1];
        s1o += acc[t][2] + acc[t][3];
        s2o += acc[t][2] * acc[t][2] + acc[t][3] * acc[t][3];
    }
#pragma unroll
    for (int off = 1; off <= 2; off <<= 1) {
        s1e += __shfl_xor_sync(0xffffffffu, s1e, off);
        s2e += __shfl_xor_sync(0xffffffffu, s2e, off);
        s1o += __shfl_xor_sync(0xffffffffu, s1o, off);
        s2o += __shfl_xor_sync(0xffffffffu, s2o, off);
    }
    float mu_e = s1e * (1.f / 128.f);
    float mu_o = s1o * (1.f / 128.f);
    float inv_e = rsqrtf(s2e * (1.f / 128.f) - mu_e * mu_e + LN_EPS);
    float inv_o = rsqrtf(s2o * (1.f / 128.f) - mu_o * mu_o + LN_EPS);

#pragma unroll
    for (int t = 0; t < 16; t++) {
        int col = 8 * t + 2 * tg;
        float2 gv = *(const float2*)(lng + col);
        float2 bv = *(const float2*)(lnb + col);
        if (r_e < NN) {
            float2 o;
            o.x = (acc[t][0] - mu_e) * inv_e * gv.x + bv.x;
            o.y = (acc[t][1] - mu_e) * inv_e * gv.y + bv.y;
            *(float2*)(nnxt + (long)r_e * HDIM + col) = o;
        }
        if (r_o < NN) {
            float2 o;
            o.x = (acc[t][2] - mu_o) * inv_o * gv.x + bv.x;
            o.y = (acc[t][3] - mu_o) * inv_o * gv.y + bv.y;
            *(float2*)(nnxt + (long)r_o * HDIM + col) = o;
        }
    }
}

// ---------------------------------------------------------------------------
// Decoder (scalar): out = relu(n @ W0 + b0) @ W1 + b1
// ---------------------------------------------------------------------------
__global__ void k_dec(const float* __restrict__ W0, const float* __restrict__ b0,
                      const float* __restrict__ W1, const float* __restrict__ b1,
                      float* __restrict__ out, int par) {
    extern __shared__ float sm[];
    float* h_s  = sm;                 // [64][132]
    float* B_s  = sm + 64 * 132;      // [32][128]
    float* A_s  = sm;                 // union, [64][33]
    float* w1_s = B_s + 32 * 128;     // [256]
    float* b1_s = w1_s + 256;         // [2]

    const float* nsrc = (par == 0) ? g_n0 : g_n1;

    const int tid = threadIdx.x;
    const int ty = tid >> 5, tx = tid & 31;
    const int m0 = ty * 8;
    const int j  = tx * 4;
    const int row0 = blockIdx.x * 64;

    float acc[8][4];
    {
        float4 bv = *(const float4*)(b0 + j);
#pragma unroll
        for (int r = 0; r < 8; r++) { acc[r][0]=bv.x; acc[r][1]=bv.y; acc[r][2]=bv.z; acc[r][3]=bv.w; }
    }
    for (int c = 0; c < 4; c++) {
        __syncthreads();
#pragma unroll
        for (int i = 0; i < 8; i++) {
            int idx = tid + i * 256;
            int m = idx >> 5, kk = idx & 31;
            int gr = row0 + m;
            A_s[m * 33 + kk] = (gr < NN) ? nsrc[gr * HDIM + c * 32 + kk] : 0.f;
        }
#pragma unroll
        for (int i = 0; i < 16; i++) B_s[tid + i * 256] = W0[c * 32 * 128 + tid + i * 256];
        __syncthreads();
        gemm_step<32, 33>(A_s, B_s, m0, j, acc);
    }
    __syncthreads();
#pragma unroll
    for (int r = 0; r < 8; r++) {
        float4 h;
        h.x = fmaxf(acc[r][0], 0.f); h.y = fmaxf(acc[r][1], 0.f);
        h.z = fmaxf(acc[r][2], 0.f); h.w = fmaxf(acc[r][3], 0.f);
        *(float4*)(h_s + (m0 + r) * 132 + j) = h;
    }
    w1_s[tid] = W1[tid];
    if (tid < 2) b1_s[tid] = b1[tid];
    __syncthreads();

    if (tid < 128) {
        int row = tid >> 1, c = tid & 1;
        float s = b1_s[c];
#pragma unroll 8
        for (int k = 0; k < 128; k++)
            s = fmaf(h_s[row * 132 + k], w1_s[k * 2 + c], s);
        int gr = row0 + row;
        if (gr < NN) out[gr * 2 + c] = s;
    }
}

// ---------------------------------------------------------------------------
extern "C" void kernel_launch(void* const* d_in, const int* in_sizes, int n_in,
                              void* d_out, int out_size) {
    const float* nodes   = (const float*)d_in[0];
    const float* edges   = (const float*)d_in[1];
    const int*   senders = (const int*)  d_in[2];
    const int*   recvs   = (const int*)  d_in[3];
    const float* enW0 = (const float*)d_in[4];
    const float* enb0 = (const float*)d_in[5];
    const float* enW1 = (const float*)d_in[6];
    const float* enb1 = (const float*)d_in[7];
    const float* eeW0 = (const float*)d_in[8];
    const float* eeb0 = (const float*)d_in[9];
    const float* eeW1 = (const float*)d_in[10];
    const float* eeb1 = (const float*)d_in[11];
    const float* Wmsg = (const float*)d_in[12];
    const float* nW0  = (const float*)d_in[13];
    const float* nb0  = (const float*)d_in[14];
    const float* nW1  = (const float*)d_in[15];
    const float* nb1  = (const float*)d_in[16];
    const float* Wnode= (const float*)d_in[17];
    const float* lng  = (const float*)d_in[18];
    const float* lnb  = (const float*)d_in[19];
    const float* dW0  = (const float*)d_in[20];
    const float* db0  = (const float*)d_in[21];
    const float* dW1  = (const float*)d_in[22];
    const float* db1  = (const float*)d_in[23];
    float* out = (float*)d_out;

    const int SM_BIG  = (64 * 132 + 32 * 128) * 4;              // 50176
    const int SM_MSG  = (64 * 33 + 32 * 128) * 4;               // 24832
    const int SM_DEC  = (64 * 132 + 32 * 128 + 256 + 2) * 4;    // 51208

    cudaFuncSetAttribute(k_node_enc,     cudaFuncAttributeMaxDynamicSharedMemorySize, SM_BIG);
    cudaFuncSetAttribute(k_cagg,         cudaFuncAttributeMaxDynamicSharedMemorySize, SM_MSG);
    cudaFuncSetAttribute(k_node_upd_mma, cudaFuncAttributeMaxDynamicSharedMemorySize, SM_MMA);
    cudaFuncSetAttribute(k_dec,          cudaFuncAttributeMaxDynamicSharedMemorySize, SM_DEC);

    // Folds, splits, CSR build, invariants
    k_fold1<<<129, 128>>>(eeW1, eeb1, Wmsg);
    k_fold2<<<257, 128>>>(nW0, Wmsg);
    k_splitB<<<64, 256>>>(nW0,   0);
    k_splitB<<<64, 256>>>(Wnode, 1);
    k_splitB<<<64, 256>>>(nW1,   2);
    k_zero_pre<<<(NN * 32 + NN / 4 + 255) / 256, 256>>>();
    k_hist<<<(NEDGE + 255) / 256, 256>>>(recvs);
    k_scan<<<1, 1024>>>();
    k_fillcsr<<<(NEDGE + 255) / 256, 256>>>(senders, recvs);
    k_node_enc<<<NODE_TILES, 256, SM_BIG>>>(nodes, enW0, enb0, enW1, enb1);
    k_edge_enc_scatter<<<EDGE_TILES, 256>>>(edges, eeW0, eeb0, recvs);
    k_cagg<<<NODE_TILES, 256, SM_MSG>>>();

    for (int p = 0; p < NPASS; p++)
        k_node_upd_mma<<<NT128, 256, SM_MMA>>>(nb0, nb1, lng, lnb, p & 1);

    k_dec<<<NODE_TILES, 256, SM_DEC>>>(dW0, db0, dW1, db1, out, NPASS & 1);
}

// round 10
// speedup vs baseline: 2.0467x; 1.0888x over previous
#include <cuda_runtime.h>
#include <cuda_bf16.h>
#include <math.h>

#define NN     50000
#define NEDGE  600000
#define HDIM   128
#define NPASS  5
#define LN_EPS 1e-6f

#define NODE_TILES ((NN + 63) / 64)     // 782  (scalar kernels)
#define NT128      ((NN + 127) / 128)   // 391  (mma tiles, nodes)
#define ET128      ((NEDGE + 127) / 128) // 4688 (mma tiles, edges)

typedef unsigned int uint32;
typedef unsigned short ushort16;

// Persistent device scratch — double-buffered node features
__device__ float g_n0[NN * HDIM];
__device__ float g_n1[NN * HDIM];
__device__ float g_hsum[NN * HDIM];
__device__ float g_cagg[NN * HDIM];
__device__ float g_T1[HDIM * HDIM];     // W1e @ Wm_bot
__device__ float g_tvec[HDIM];          // b1e @ Wm_bot
__device__ float g_Wg[HDIM * HDIM];     // (W1e @ Wm_bot) @ W0_bot
__device__ float g_bg[HDIM];

// Receiver-CSR of the edge list (built once per launch)
__device__ int g_rowptr[NN + 1];
__device__ int g_cursor[NN];
__device__ int g_col[NEDGE];

// Split-bf16 weight tables, [N][K] k-contiguous (transposed)
__device__ __align__(16) ushort16 g_BtopH[HDIM * HDIM], g_BtopL[HDIM * HDIM]; // W0_top
__device__ __align__(16) ushort16 g_BWfH [HDIM * HDIM], g_BWfL [HDIM * HDIM]; // Wm_top@W0_bot
__device__ __align__(16) ushort16 g_BresH[HDIM * HDIM], g_BresL[HDIM * HDIM]; // Wn
__device__ __align__(16) ushort16 g_BoutH[HDIM * HDIM], g_BoutL[HDIM * HDIM]; // W1
__device__ __align__(16) ushort16 g_BeH[HDIM * 16],     g_BeL[HDIM * 16];     // W0_edge [n][16k]

// ---------------------------------------------------------------------------
// Scalar register-tiled GEMM micro-step — used by enc/cagg/dec
// ---------------------------------------------------------------------------
template<int KC, int LDA>
__device__ __forceinline__ void gemm_step(const float* __restrict__ A_s,
                                          const float* __restrict__ B_s,
                                          int m0, int j, float acc[8][4]) {
#pragma unroll 8
    for (int kk = 0; kk < KC; kk++) {
        float4 b = *(const float4*)(B_s + kk * HDIM + j);
#pragma unroll
        for (int r = 0; r < 8; r++) {
            float a = A_s[(m0 + r) * LDA + kk];
            acc[r][0] = fmaf(a, b.x, acc[r][0]);
            acc[r][1] = fmaf(a, b.y, acc[r][1]);
            acc[r][2] = fmaf(a, b.z, acc[r][2]);
            acc[r][3] = fmaf(a, b.w, acc[r][3]);
        }
    }
}

// ---------------------------------------------------------------------------
// bf16 helpers + MMA
// ---------------------------------------------------------------------------
__device__ __forceinline__ uint32 pack_bf2(float x, float y) {
    __nv_bfloat162 t = __floats2bfloat162_rn(x, y);
    return *reinterpret_cast<uint32*>(&t);
}
__device__ __forceinline__ void split_bf(float v, ushort16& h, ushort16& l) {
    __nv_bfloat16 hb = __float2bfloat16_rn(v);
    float lo = v - __bfloat162float(hb);
    __nv_bfloat16 lb = __float2bfloat16_rn(lo);
    h = *reinterpret_cast<ushort16*>(&hb);
    l = *reinterpret_cast<ushort16*>(&lb);
}
// pack float2 -> (hi u32, lo u32)
__device__ __forceinline__ void split_pack2(float2 v, uint32& h, uint32& l) {
    float ex = __bfloat162float(__float2bfloat16_rn(v.x));
    float ey = __bfloat162float(__float2bfloat16_rn(v.y));
    h = pack_bf2(v.x, v.y);
    l = pack_bf2(v.x - ex, v.y - ey);
}
#define MMA16816(d, a0,a1,a2,a3, b0,b1) \
    asm volatile("mma.sync.aligned.m16n8k16.row.col.f32.bf16.bf16.f32 " \
        "{%0,%1,%2,%3},{%4,%5,%6,%7},{%8,%9},{%0,%1,%2,%3};" \
        : "+f"((d)[0]), "+f"((d)[1]), "+f"((d)[2]), "+f"((d)[3]) \
        : "r"(a0), "r"(a1), "r"(a2), "r"(a3), "r"(b0), "r"(b1))

// ---------------------------------------------------------------------------
// Weight folds
// ---------------------------------------------------------------------------
__global__ void k_fold1(const float* __restrict__ W1e, const float* __restrict__ b1e,
                        const float* __restrict__ Wm) {
    __shared__ float a[HDIM];
    int j = threadIdx.x;
    a[j] = (blockIdx.x < 128) ? W1e[blockIdx.x * HDIM + j] : b1e[j];
    __syncthreads();
    float s = 0.f;
#pragma unroll 8
    for (int l = 0; l < HDIM; l++)
        s = fmaf(a[l], Wm[(HDIM + l) * HDIM + j], s);
    if (blockIdx.x < 128) g_T1[blockIdx.x * HDIM + j] = s;
    else                  g_tvec[j] = s;
}

__global__ void k_fold2(const float* __restrict__ W0n, const float* __restrict__ Wm) {
    __shared__ float a[HDIM];
    int j = threadIdx.x;
    int bid = blockIdx.x;
    if (bid < 128)       a[j] = g_T1[bid * HDIM + j];
    else if (bid == 128) a[j] = g_tvec[j];
    else                 a[j] = Wm[(bid - 129) * HDIM + j];
    __syncthreads();
    float s = 0.f;
#pragma unroll 8
    for (int l = 0; l < HDIM; l++)
        s = fmaf(a[l], W0n[(HDIM + l) * HDIM + j], s);
    if (bid < 128)       g_Wg[bid * HDIM + j] = s;
    else if (bid == 128) g_bg[j] = s;
    else {
        int k = bid - 129;
        ushort16 h, l2; split_bf(s, h, l2);
        g_BWfH[j * HDIM + k] = h;
        g_BWfL[j * HDIM + k] = l2;
    }
}

// Merged split of the three [128][128] node weights; dest picked in device code.
__global__ void k_splitB(const float* __restrict__ W0, const float* __restrict__ Wn,
                         const float* __restrict__ W1) {
    int which = blockIdx.x >> 6;
    const float* W; ushort16* dH; ushort16* dL;
    if (which == 0)      { W = W0; dH = g_BtopH; dL = g_BtopL; }
    else if (which == 1) { W = Wn; dH = g_BresH; dL = g_BresL; }
    else                 { W = W1; dH = g_BoutH; dL = g_BoutL; }
    int idx = (blockIdx.x & 63) * 256 + threadIdx.x;
    int k = idx >> 7, n = idx & 127;
    ushort16 h, l;
    split_bf(W[k * HDIM + n], h, l);
    dH[n * HDIM + k] = h;
    dL[n * HDIM + k] = l;
}

// Split + transpose edge weight W0e [16][128] -> [n][16k]
__global__ void k_splitE(const float* __restrict__ W0e) {
    int idx = blockIdx.x * 256 + threadIdx.x;   // 2048
    int n = idx & 127, k = idx >> 7;
    ushort16 h, l;
    split_bf(W0e[k * HDIM + n], h, l);
    g_BeH[n * 16 + k] = h;
    g_BeL[n * 16 + k] = l;
}

// ---------------------------------------------------------------------------
// CSR build + zero helpers
// ---------------------------------------------------------------------------
__global__ void k_zero_pre() {   // zero g_hsum (float4) and g_cursor (int4)
    int i = blockIdx.x * blockDim.x + threadIdx.x;
    if (i < NN * 32) ((float4*)g_hsum)[i] = make_float4(0.f, 0.f, 0.f, 0.f);
    else {
        int d = i - NN * 32;
        if (d < NN / 4) ((int4*)g_cursor)[d] = make_int4(0, 0, 0, 0);
    }
}

__global__ void k_hist(const int* __restrict__ recvs) {
    int e = blockIdx.x * 256 + threadIdx.x;
    if (e < NEDGE) atomicAdd(g_cursor + recvs[e], 1);
}

__global__ void __launch_bounds__(1024) k_scan() {
    __shared__ int partial[1024];
    const int CHUNK = (NN + 1023) / 1024;
    int t = threadIdx.x;
    int beg = t * CHUNK, end = min(beg + CHUNK, NN);
    int s = 0;
    for (int i = beg; i < end; i++) s += g_cursor[i];
    partial[t] = s;
    __syncthreads();
    for (int off = 1; off < 1024; off <<= 1) {
        int v = (t >= off) ? partial[t - off] : 0;
        __syncthreads();
        partial[t] += v;
        __syncthreads();
    }
    int base = (t > 0) ? partial[t - 1] : 0;
    for (int i = beg; i < end; i++) {
        int c = g_cursor[i];
        g_rowptr[i] = base;
        g_cursor[i] = base;
        base += c;
    }
    if (t == 1023) g_rowptr[NN] = partial[1023];
}

__global__ void k_fillcsr(const int* __restrict__ senders,
                          const int* __restrict__ recvs) {
    int e = blockIdx.x * 256 + threadIdx.x;
    if (e < NEDGE) {
        int pos = atomicAdd(g_cursor + recvs[e], 1);
        g_col[pos] = senders[e];
    }
}

// ---------------------------------------------------------------------------
// Node encoder (scalar): n0 = relu(x@W0+b0)@W1+b1
// ---------------------------------------------------------------------------
__global__ void k_node_enc(const float* __restrict__ x,
                           const float* __restrict__ W0, const float* __restrict__ b0,
                           const float* __restrict__ W1, const float* __restrict__ b1) {
    extern __shared__ float sm[];
    float* h_s = sm;                 // [64][132]
    float* B_s = sm + 64 * 132;      // [32][128]
    float* A_s = sm;                 // union, [64][33]

    const int tid = threadIdx.x;
    const int ty = tid >> 5, tx = tid & 31;
    const int m0 = ty * 8;
    const int j  = tx * 4;
    const int row0 = blockIdx.x * 64;

#pragma unroll
    for (int i = 0; i < 8; i++) {
        int idx = tid + i * 256;
        int m = idx >> 5, kk = idx & 31;
        int gr = row0 + m;
        A_s[m * 33 + kk] = (gr < NN) ? x[gr * 32 + kk] : 0.f;
    }
#pragma unroll
    for (int i = 0; i < 16; i++) B_s[tid + i * 256] = W0[tid + i * 256];
    __syncthreads();

    float acc[8][4];
    {
        float4 bv = *(const float4*)(b0 + j);
#pragma unroll
        for (int r = 0; r < 8; r++) { acc[r][0]=bv.x; acc[r][1]=bv.y; acc[r][2]=bv.z; acc[r][3]=bv.w; }
    }
    gemm_step<32, 33>(A_s, B_s, m0, j, acc);
    __syncthreads();

#pragma unroll
    for (int r = 0; r < 8; r++) {
        float4 h;
        h.x = fmaxf(acc[r][0], 0.f); h.y = fmaxf(acc[r][1], 0.f);
        h.z = fmaxf(acc[r][2], 0.f); h.w = fmaxf(acc[r][3], 0.f);
        *(float4*)(h_s + (m0 + r) * 132 + j) = h;
    }

    float o[8][4];
    {
        float4 bv = *(const float4*)(b1 + j);
#pragma unroll
        for (int r = 0; r < 8; r++) { o[r][0]=bv.x; o[r][1]=bv.y; o[r][2]=bv.z; o[r][3]=bv.w; }
    }
    for (int c = 0; c < 4; c++) {
        __syncthreads();
#pragma unroll
        for (int i = 0; i < 16; i++) B_s[tid + i * 256] = W1[c * 32 * 128 + tid + i * 256];
        __syncthreads();
        gemm_step<32, 132>(h_s + c * 32, B_s, m0, j, o);
    }
#pragma unroll
    for (int r = 0; r < 8; r++) {
        int gr = row0 + m0 + r;
        if (gr < NN)
            *(float4*)(g_n0 + gr * HDIM + j) = make_float4(o[r][0], o[r][1], o[r][2], o[r][3]);
    }
}

// ===========================================================================
// MMA edge encoder + scatter: h = relu(x@W0e+b0e); g_hsum[recv] += h
// Block = 128 edges x 128 cols, 8 warps. K=16, A fragments direct from gmem.
// ===========================================================================
#define SM_EDGE ((1024 + 1024 + 128 * 132) * 4)   // 75776 B

__global__ void __launch_bounds__(256, 2) k_edge_mma(
        const float* __restrict__ x, const float* __restrict__ b0e,
        const int* __restrict__ recvs) {
    extern __shared__ uint32 smu[];
    uint32* BhU  = smu;              // [128][8]
    uint32* BlU  = smu + 1024;
    float*  Hout = (float*)(smu + 2048);  // [128][132]

    const int tid = threadIdx.x;
    const int w = tid >> 5, lane = tid & 31;
    const int gid = lane >> 2, tg = lane & 3;
    const int rw0 = w * 16;
    const int row0 = blockIdx.x * 128;
    const int eE = row0 + rw0 + gid;
    const int eO = eE + 8;

    // fill B fragments (split table, [n][8 u32])
#pragma unroll
    for (int i = 0; i < 4; i++) {
        int p = tid + i * 256;
        BhU[p] = ((const uint32*)g_BeH)[p];
        BlU[p] = ((const uint32*)g_BeL)[p];
    }

    // A fragments direct from gmem (K=16): rows eE/eO, k pairs (2tg, 2tg+1) and +8
    float2 z = make_float2(0.f, 0.f);
    float2 vE0 = (eE < NEDGE) ? *(const float2*)(x + (long)eE * 16 + 2 * tg)     : z;
    float2 vE1 = (eE < NEDGE) ? *(const float2*)(x + (long)eE * 16 + 8 + 2 * tg) : z;
    float2 vO0 = (eO < NEDGE) ? *(const float2*)(x + (long)eO * 16 + 2 * tg)     : z;
    float2 vO1 = (eO < NEDGE) ? *(const float2*)(x + (long)eO * 16 + 8 + 2 * tg) : z;
    uint32 ah0, al0, ah1, al1, ah2, al2, ah3, al3;
    split_pack2(vE0, ah0, al0);
    split_pack2(vO0, ah1, al1);
    split_pack2(vE1, ah2, al2);
    split_pack2(vO1, ah3, al3);
    __syncthreads();

    float acc[16][4];
#pragma unroll
    for (int t = 0; t < 16; t++) {
        int col = 8 * t + 2 * tg;
        float2 bb = *(const float2*)(b0e + col);
        acc[t][0] = bb.x; acc[t][1] = bb.y;
        acc[t][2] = bb.x; acc[t][3] = bb.y;
    }
#pragma unroll
    for (int t = 0; t < 16; t++) {
        int bi = (8 * t + gid) * 8 + tg;
        uint32 bh0 = BhU[bi], bh1 = BhU[bi + 4];
        uint32 bl0 = BlU[bi], bl1 = BlU[bi + 4];
        MMA16816(acc[t], ah0, ah1, ah2, ah3, bh0, bh1);
        MMA16816(acc[t], ah0, ah1, ah2, ah3, bl0, bl1);
        MMA16816(acc[t], al0, al1, al2, al3, bh0, bh1);
    }

    // relu -> smem
#pragma unroll
    for (int t = 0; t < 16; t++) {
        int col = 8 * t + 2 * tg;
        *(float2*)(Hout + (rw0 + gid)     * 132 + col) =
            make_float2(fmaxf(acc[t][0], 0.f), fmaxf(acc[t][1], 0.f));
        *(float2*)(Hout + (rw0 + gid + 8) * 132 + col) =
            make_float2(fmaxf(acc[t][2], 0.f), fmaxf(acc[t][3], 0.f));
    }
    __syncthreads();

    // scatter: warp rows rw0..rw0+15, lanes cover 128 cols
    int j = lane * 4;
    for (int r = 0; r < 16; r++) {
        int e = row0 + rw0 + r;
        if (e < NEDGE) {
            int rv = __ldg(recvs + e);
            float4 v = *(const float4*)(Hout + (rw0 + r) * 132 + j);
            float* dst = g_hsum + (long)rv * HDIM + j;
            asm volatile("red.global.add.v4.f32 [%0], {%1, %2, %3, %4};"
                         :: "l"(dst), "f"(v.x), "f"(v.y), "f"(v.z), "f"(v.w) : "memory");
        }
    }
}

// ---------------------------------------------------------------------------
// c_agg = g_hsum @ g_Wg + deg * g_bg   (deg from rowptr diffs)
// ---------------------------------------------------------------------------
__global__ void k_cagg() {
    extern __shared__ float sm[];
    float* A_s = sm;                 // [64][33]
    float* B_s = sm + 64 * 33;       // [32][128]

    const int tid = threadIdx.x;
    const int ty = tid >> 5, tx = tid & 31;
    const int m0 = ty * 8;
    const int j  = tx * 4;
    const int row0 = blockIdx.x * 64;

    float acc[8][4];
    {
        float4 bgv = *(const float4*)(g_bg + j);
#pragma unroll
        for (int r = 0; r < 8; r++) {
            int gr = row0 + m0 + r;
            float d = (gr < NN) ? (float)(g_rowptr[gr + 1] - g_rowptr[gr]) : 0.f;
            acc[r][0] = d * bgv.x; acc[r][1] = d * bgv.y;
            acc[r][2] = d * bgv.z; acc[r][3] = d * bgv.w;
        }
    }
    for (int c = 0; c < 4; c++) {
        __syncthreads();
#pragma unroll
        for (int i = 0; i < 8; i++) {
            int idx = tid + i * 256;
            int m = idx >> 5, kk = idx & 31;
            int gr = row0 + m;
            A_s[m * 33 + kk] = (gr < NN) ? g_hsum[gr * HDIM + c * 32 + kk] : 0.f;
        }
#pragma unroll
        for (int i = 0; i < 16; i++) B_s[tid + i * 256] = g_Wg[c * 32 * 128 + tid + i * 256];
        __syncthreads();
        gemm_step<32, 33>(A_s, B_s, m0, j, acc);
    }
#pragma unroll
    for (int r = 0; r < 8; r++) {
        int gr = row0 + m0 + r;
        if (gr < NN)
            *(float4*)(g_cagg + gr * HDIM + j) =
                make_float4(acc[r][0], acc[r][1], acc[r][2], acc[r][3]);
    }
}

// ===========================================================================
// Fused MMA node update (CSR gather with row-paired MLP8)
// ===========================================================================
#define BST 20
#define U_AH 0
#define U_AL (U_AH + 128 * BST)
#define U_BH (U_AL + 128 * BST)
#define U_BL (U_BH + 128 * BST)
#define U_HH (U_BL + 128 * BST)
#define U_HL (U_HH + 128 * 68)
#define U_END (U_HL + 128 * 68)
#define SM_MMA (U_END * 4)          // 110592 bytes

__device__ __forceinline__ void fillA(uint32* AhU, uint32* AlU,
                                      const float* __restrict__ src,
                                      int row0, int koff, int tid) {
#pragma unroll
    for (int i = 0; i < 4; i++) {
        int p = tid + i * 256;
        int row = p >> 3, q = p & 7;
        int gr = row0 + row;
        float4 v = make_float4(0.f, 0.f, 0.f, 0.f);
        if (gr < NN) v = *(const float4*)(src + (long)gr * HDIM + koff + 4 * q);
        float ex = __bfloat162float(__float2bfloat16_rn(v.x));
        float ey = __bfloat162float(__float2bfloat16_rn(v.y));
        float ez = __bfloat162float(__float2bfloat16_rn(v.z));
        float ew = __bfloat162float(__float2bfloat16_rn(v.w));
        uint2 hh = make_uint2(pack_bf2(v.x, v.y), pack_bf2(v.z, v.w));
        uint2 ll = make_uint2(pack_bf2(v.x - ex, v.y - ey), pack_bf2(v.z - ez, v.w - ew));
        *(uint2*)(AhU + row * BST + 2 * q) = hh;
        *(uint2*)(AlU + row * BST + 2 * q) = ll;
    }
}

__device__ __forceinline__ void fillB(uint32* BhU, uint32* BlU,
                                      const ushort16* __restrict__ gH,
                                      const ushort16* __restrict__ gL,
                                      int koff, int tid) {
    const uint4* sH = (const uint4*)gH;
    const uint4* sL = (const uint4*)gL;
    int kq0 = koff >> 3;
#pragma unroll
    for (int i = 0; i < 2; i++) {
        int p = tid + i * 256;
        int n = p >> 2, kq = p & 3;
        uint4 vh = sH[n * 16 + kq0 + kq];
        uint4 vl = sL[n * 16 + kq0 + kq];
        *(uint4*)(BhU + n * BST + 4 * kq) = vh;
        *(uint4*)(BlU + n * BST + 4 * kq) = vl;
    }
}

template<int AS>
__device__ __forceinline__ void mma_chunk(const uint32* AhU, const uint32* AlU,
                                          const uint32* BhU, const uint32* BlU,
                                          float acc[16][4], int rw0, int gid, int tg) {
#pragma unroll
    for (int kb2 = 0; kb2 <= 8; kb2 += 8) {
        int a0i = (rw0 + gid) * AS + kb2 + tg;
        int a1i = a0i + 8 * AS;
        uint32 ah0 = AhU[a0i],     ah1 = AhU[a1i];
        uint32 ah2 = AhU[a0i + 4], ah3 = AhU[a1i + 4];
        uint32 al0 = AlU[a0i],     al1 = AlU[a1i];
        uint32 al2 = AlU[a0i + 4], al3 = AlU[a1i + 4];
#pragma unroll
        for (int t = 0; t < 16; t++) {
            int bi = (8 * t + gid) * BST + kb2 + tg;
            uint32 bh0 = BhU[bi], bh1 = BhU[bi + 4];
            uint32 bl0 = BlU[bi], bl1 = BlU[bi + 4];
            MMA16816(acc[t], ah0, ah1, ah2, ah3, bh0, bh1);
            MMA16816(acc[t], ah0, ah1, ah2, ah3, bl0, bl1);
            MMA16816(acc[t], al0, al1, al2, al3, bh0, bh1);
        }
    }
}

__global__ void __launch_bounds__(256, 2) k_node_upd_mma(
        const float* __restrict__ b0, const float* __restrict__ b1,
        const float* __restrict__ lng, const float* __restrict__ lnb,
        int par) {
    extern __shared__ uint32 smu[];
    uint32* AhU = smu + U_AH;
    uint32* AlU = smu + U_AL;
    uint32* BhU = smu + U_BH;
    uint32* BlU = smu + U_BL;
    uint32* HhU = smu + U_HH;
    uint32* HlU = smu + U_HL;

    const float* ncur = (par == 0) ? g_n0 : g_n1;
    float*       nnxt = (par == 0) ? g_n1 : g_n0;

    const int tid = threadIdx.x;
    const int w = tid >> 5, lane = tid & 31;
    const int gid = lane >> 2, tg = lane & 3;
    const int rw0 = w * 16;
    const int row0 = blockIdx.x * 128;
    const int r_e = row0 + rw0 + gid;
    const int r_o = r_e + 8;
    const int jj = lane * 4;

    // ---- CSR gather, row-paired (rr, rr+8) for MLP8 ----
    for (int rr = 0; rr < 8; rr++) {
        int rowA = rw0 + rr, rowB = rowA + 8;
        int grA = row0 + rowA, grB = row0 + rowB;
        float A0 = 0.f, A1 = 0.f, A2 = 0.f, A3 = 0.f;
        float B0 = 0.f, B1 = 0.f, B2 = 0.f, B3 = 0.f;
        int eA = 0, nA = 0, eB = 0, nB = 0;
        if (grA < NN) { eA = g_rowptr[grA]; nA = g_rowptr[grA + 1]; }
        if (grB < NN) { eB = g_rowptr[grB]; nB = g_rowptr[grB + 1]; }
        while (eA + 4 <= nA && eB + 4 <= nB) {
            int a0 = g_col[eA], a1 = g_col[eA+1], a2 = g_col[eA+2], a3 = g_col[eA+3];
            int b0i = g_col[eB], b1i = g_col[eB+1], b2i = g_col[eB+2], b3i = g_col[eB+3];
            float4 u0 = *(const float4*)(ncur + (long)a0 * HDIM + jj);
            float4 u1 = *(const float4*)(ncur + (long)a1 * HDIM + jj);
            float4 u2 = *(const float4*)(ncur + (long)a2 * HDIM + jj);
            float4 u3 = *(const float4*)(ncur + (long)a3 * HDIM + jj);
            float4 w0 = *(const float4*)(ncur + (long)b0i * HDIM + jj);
            float4 w1 = *(const float4*)(ncur + (long)b1i * HDIM + jj);
            float4 w2 = *(const float4*)(ncur + (long)b2i * HDIM + jj);
            float4 w3 = *(const float4*)(ncur + (long)b3i * HDIM + jj);
            A0 += u0.x + u1.x + u2.x + u3.x;
            A1 += u0.y + u1.y + u2.y + u3.y;
            A2 += u0.z + u1.z + u2.z + u3.z;
            A3 += u0.w + u1.w + u2.w + u3.w;
            B0 += w0.x + w1.x + w2.x + w3.x;
            B1 += w0.y + w1.y + w2.y + w3.y;
            B2 += w0.z + w1.z + w2.z + w3.z;
            B3 += w0.w + w1.w + w2.w + w3.w;
            eA += 4; eB += 4;
        }
        for (; eA + 4 <= nA; eA += 4) {
            int a0 = g_col[eA], a1 = g_col[eA+1], a2 = g_col[eA+2], a3 = g_col[eA+3];
            float4 u0 = *(const float4*)(ncur + (long)a0 * HDIM + jj);
            float4 u1 = *(const float4*)(ncur + (long)a1 * HDIM + jj);
            float4 u2 = *(const float4*)(ncur + (long)a2 * HDIM + jj);
            float4 u3 = *(const float4*)(ncur + (long)a3 * HDIM + jj);
            A0 += u0.x + u1.x + u2.x + u3.x;
            A1 += u0.y + u1.y + u2.y + u3.y;
            A2 += u0.z + u1.z + u2.z + u3.z;
            A3 += u0.w + u1.w + u2.w + u3.w;
        }
        for (; eA < nA; eA++) {
            int s = g_col[eA];
            float4 v = *(const float4*)(ncur + (long)s * HDIM + jj);
            A0 += v.x; A1 += v.y; A2 += v.z; A3 += v.w;
        }
        for (; eB + 4 <= nB; eB += 4) {
            int b0i = g_col[eB], b1i = g_col[eB+1], b2i = g_col[eB+2], b3i = g_col[eB+3];
            float4 w0 = *(const float4*)(ncur + (long)b0i * HDIM + jj);
            float4 w1 = *(const float4*)(ncur + (long)b1i * HDIM + jj);
            float4 w2 = *(const float4*)(ncur + (long)b2i * HDIM + jj);
            float4 w3 = *(const float4*)(ncur + (long)b3i * HDIM + jj);
            B0 += w0.x + w1.x + w2.x + w3.x;
            B1 += w0.y + w1.y + w2.y + w3.y;
            B2 += w0.z + w1.z + w2.z + w3.z;
            B3 += w0.w + w1.w + w2.w + w3.w;
        }
        for (; eB < nB; eB++) {
            int s = g_col[eB];
            float4 v = *(const float4*)(ncur + (long)s * HDIM + jj);
            B0 += v.x; B1 += v.y; B2 += v.z; B3 += v.w;
        }
        uint32 h0, l0, h1, l1;
        split_pack2(make_float2(A0, A1), h0, l0);
        split_pack2(make_float2(A2, A3), h1, l1);
        *(uint2*)(HhU + rowA * 68 + lane * 2) = make_uint2(h0, h1);
        *(uint2*)(HlU + rowA * 68 + lane * 2) = make_uint2(l0, l1);
        split_pack2(make_float2(B0, B1), h0, l0);
        split_pack2(make_float2(B2, B3), h1, l1);
        *(uint2*)(HhU + rowB * 68 + lane * 2) = make_uint2(h0, h1);
        *(uint2*)(HlU + rowB * 68 + lane * 2) = make_uint2(l0, l1);
    }

    float acc[16][4];

    // ---- hidden accumulator init: b0 + c_agg ----
#pragma unroll
    for (int t = 0; t < 16; t++) {
        int col = 8 * t + 2 * tg;
        float2 bb = *(const float2*)(b0 + col);
        float2 ce = (r_e < NN) ? *(const float2*)(g_cagg + (long)r_e * HDIM + col)
                               : make_float2(0.f, 0.f);
        float2 co = (r_o < NN) ? *(const float2*)(g_cagg + (long)r_o * HDIM + col)
                               : make_float2(0.f, 0.f);
        acc[t][0] = bb.x + ce.x; acc[t][1] = bb.y + ce.y;
        acc[t][2] = bb.x + co.x; acc[t][3] = bb.y + co.y;
    }

    // ---- hidden: K = 256 — n chunks from gmem, S chunks from H ----
    for (int c = 0; c < 8; c++) {
        int koff = (c & 3) * 32;
        __syncthreads();
        if (c < 4) fillA(AhU, AlU, ncur, row0, koff, tid);
        fillB(BhU, BlU, (c < 4) ? g_BtopH : g_BWfH,
                        (c < 4) ? g_BtopL : g_BWfL, koff, tid);
        __syncthreads();
        if (c < 4) mma_chunk<BST>(AhU, AlU, BhU, BlU, acc, rw0, gid, tg);
        else       mma_chunk<68>(HhU + 16 * (c - 4), HlU + 16 * (c - 4),
                                 BhU, BlU, acc, rw0, gid, tg);
    }

    // ---- relu + split-store h to smem H ----
    __syncthreads();
#pragma unroll
    for (int t = 0; t < 16; t++) {
        float h0 = fmaxf(acc[t][0], 0.f), h1 = fmaxf(acc[t][1], 0.f);
        float h2 = fmaxf(acc[t][2], 0.f), h3 = fmaxf(acc[t][3], 0.f);
        int ie = (rw0 + gid) * 68 + 4 * t + tg;
        int io = ie + 8 * 68;
        float e0 = __bfloat162float(__float2bfloat16_rn(h0));
        float e1 = __bfloat162float(__float2bfloat16_rn(h1));
        float e2 = __bfloat162float(__float2bfloat16_rn(h2));
        float e3 = __bfloat162float(__float2bfloat16_rn(h3));
        HhU[ie] = pack_bf2(h0, h1);
        HlU[ie] = pack_bf2(h0 - e0, h1 - e1);
        HhU[io] = pack_bf2(h2, h3);
        HlU[io] = pack_bf2(h2 - e2, h3 - e3);
    }

    // ---- residual: acc = n @ Wn ----
#pragma unroll
    for (int t = 0; t < 16; t++) {
        acc[t][0] = 0.f; acc[t][1] = 0.f; acc[t][2] = 0.f; acc[t][3] = 0.f;
    }
    for (int c = 0; c < 4; c++) {
        __syncthreads();
        fillA(AhU, AlU, ncur, row0, c * 32, tid);
        fillB(BhU, BlU, g_BresH, g_BresL, c * 32, tid);
        __syncthreads();
        mma_chunk<BST>(AhU, AlU, BhU, BlU, acc, rw0, gid, tg);
    }

    // ---- output: acc += h @ W1 ----
    for (int c = 0; c < 4; c++) {
        __syncthreads();
        fillB(BhU, BlU, g_BoutH, g_BoutL, c * 32, tid);
        __syncthreads();
        mma_chunk<68>(HhU + 16 * c, HlU + 16 * c, BhU, BlU, acc, rw0, gid, tg);
    }

    // ---- + b1, LayerNorm, write other buffer ----
    float s1e = 0.f, s2e = 0.f, s1o = 0.f, s2o = 0.f;
#pragma unroll
    for (int t = 0; t < 16; t++) {
        int col = 8 * t + 2 * tg;
        float2 bb = *(const float2*)(b1 + col);
        acc[t][0] += bb.x; acc[t][1] += bb.y;
        acc[t][2] += bb.x; acc[t][3] += bb.y;
        s1e += acc[t][0] + acc[t][1];
        s2e += acc[t][0] * acc[t][0] + acc[t][1] * acc[t][1];
        s1o += acc[t][2] + acc[t][3];
        s2o += acc[t][2] * acc[t][2] + acc[t][3] * acc[t][3];
    }
#pragma unroll
    for (int off = 1; off <= 2; off <<= 1) {
        s1e += __shfl_xor_sync(0xffffffffu, s1e, off);
        s2e += __shfl_xor_sync(0xffffffffu, s2e, off);
        s1o += __shfl_xor_sync(0xffffffffu, s1o, off);
        s2o += __shfl_xor_sync(0xffffffffu, s2o, off);
    }
    float mu_e = s1e * (1.f / 128.f);
    float mu_o = s1o * (1.f / 128.f);
    float inv_e = rsqrtf(s2e * (1.f / 128.f) - mu_e * mu_e + LN_EPS);
    float inv_o = rsqrtf(s2o * (1.f / 128.f) - mu_o * mu_o + LN_EPS);

#pragma unroll
    for (int t = 0; t < 16; t++) {
        int col = 8 * t + 2 * tg;
        float2 gv = *(const float2*)(lng + col);
        float2 bv = *(const float2*)(lnb + col);
        if (r_e < NN) {
            float2 o;
            o.x = (acc[t][0] - mu_e) * inv_e * gv.x + bv.x;
            o.y = (acc[t][1] - mu_e) * inv_e * gv.y + bv.y;
            *(float2*)(nnxt + (long)r_e * HDIM + col) = o;
        }
        if (r_o < NN) {
            float2 o;
            o.x = (acc[t][2] - mu_o) * inv_o * gv.x + bv.x;
            o.y = (acc[t][3] - mu_o) * inv_o * gv.y + bv.y;
            *(float2*)(nnxt + (long)r_o * HDIM + col) = o;
        }
    }
}

// ---------------------------------------------------------------------------
// Decoder (scalar): out = relu(n @ W0 + b0) @ W1 + b1
// ---------------------------------------------------------------------------
__global__ void k_dec(const float* __restrict__ W0, const float* __restrict__ b0,
                      const float* __restrict__ W1, const float* __restrict__ b1,
                      float* __restrict__ out, int par) {
    extern __shared__ float sm[];
    float* h_s  = sm;
    float* B_s  = sm + 64 * 132;
    float* A_s  = sm;
    float* w1_s = B_s + 32 * 128;
    float* b1_s = w1_s + 256;

    const float* nsrc = (par == 0) ? g_n0 : g_n1;

    const int tid = threadIdx.x;
    const int ty = tid >> 5, tx = tid & 31;
    const int m0 = ty * 8;
    const int j  = tx * 4;
    const int row0 = blockIdx.x * 64;

    float acc[8][4];
    {
        float4 bv = *(const float4*)(b0 + j);
#pragma unroll
        for (int r = 0; r < 8; r++) { acc[r][0]=bv.x; acc[r][1]=bv.y; acc[r][2]=bv.z; acc[r][3]=bv.w; }
    }
    for (int c = 0; c < 4; c++) {
        __syncthreads();
#pragma unroll
        for (int i = 0; i < 8; i++) {
            int idx = tid + i * 256;
            int m = idx >> 5, kk = idx & 31;
            int gr = row0 + m;
            A_s[m * 33 + kk] = (gr < NN) ? nsrc[gr * HDIM + c * 32 + kk] : 0.f;
        }
#pragma unroll
        for (int i = 0; i < 16; i++) B_s[tid + i * 256] = W0[c * 32 * 128 + tid + i * 256];
        __syncthreads();
        gemm_step<32, 33>(A_s, B_s, m0, j, acc);
    }
    __syncthreads();
#pragma unroll
    for (int r = 0; r < 8; r++) {
        float4 h;
        h.x = fmaxf(acc[r][0], 0.f); h.y = fmaxf(acc[r][1], 0.f);
        h.z = fmaxf(acc[r][2], 0.f); h.w = fmaxf(acc[r][3], 0.f);
        *(float4*)(h_s + (m0 + r) * 132 + j) = h;
    }
    w1_s[tid] = W1[tid];
    if (tid < 2) b1_s[tid] = b1[tid];
    __syncthreads();

    if (tid < 128) {
        int row = tid >> 1, c = tid & 1;
        float s = b1_s[c];
#pragma unroll 8
        for (int k = 0; k < 128; k++)
            s = fmaf(h_s[row * 132 + k], w1_s[k * 2 + c], s);
        int gr = row0 + row;
        if (gr < NN) out[gr * 2 + c] = s;
    }
}

// ---------------------------------------------------------------------------
extern "C" void kernel_launch(void* const* d_in, const int* in_sizes, int n_in,
                              void* d_out, int out_size) {
    const float* nodes   = (const float*)d_in[0];
    const float* edges   = (const float*)d_in[1];
    const int*   senders = (const int*)  d_in[2];
    const int*   recvs   = (const int*)  d_in[3];
    const float* enW0 = (const float*)d_in[4];
    const float* enb0 = (const float*)d_in[5];
    const float* enW1 = (const float*)d_in[6];
    const float* enb1 = (const float*)d_in[7];
    const float* eeW0 = (const float*)d_in[8];
    const float* eeb0 = (const float*)d_in[9];
    const float* eeW1 = (const float*)d_in[10];
    const float* eeb1 = (const float*)d_in[11];
    const float* Wmsg = (const float*)d_in[12];
    const float* nW0  = (const float*)d_in[13];
    const float* nb0  = (const float*)d_in[14];
    const float* nW1  = (const float*)d_in[15];
    const float* nb1  = (const float*)d_in[16];
    const float* Wnode= (const float*)d_in[17];
    const float* lng  = (const float*)d_in[18];
    const float* lnb  = (const float*)d_in[19];
    const float* dW0  = (const float*)d_in[20];
    const float* db0  = (const float*)d_in[21];
    const float* dW1  = (const float*)d_in[22];
    const float* db1  = (const float*)d_in[23];
    float* out = (float*)d_out;

    const int SM_BIG  = (64 * 132 + 32 * 128) * 4;
    const int SM_MSG  = (64 * 33 + 32 * 128) * 4;
    const int SM_DEC  = (64 * 132 + 32 * 128 + 256 + 2) * 4;

    cudaFuncSetAttribute(k_node_enc,     cudaFuncAttributeMaxDynamicSharedMemorySize, SM_BIG);
    cudaFuncSetAttribute(k_edge_mma,     cudaFuncAttributeMaxDynamicSharedMemorySize, SM_EDGE);
    cudaFuncSetAttribute(k_cagg,         cudaFuncAttributeMaxDynamicSharedMemorySize, SM_MSG);
    cudaFuncSetAttribute(k_node_upd_mma, cudaFuncAttributeMaxDynamicSharedMemorySize, SM_MMA);
    cudaFuncSetAttribute(k_dec,          cudaFuncAttributeMaxDynamicSharedMemorySize, SM_DEC);

    // Folds, splits, CSR build, invariants
    k_fold1<<<129, 128>>>(eeW1, eeb1, Wmsg);
    k_fold2<<<257, 128>>>(nW0, Wmsg);
    k_splitB<<<192, 256>>>(nW0, Wnode, nW1);
    k_splitE<<<8, 256>>>(eeW0);
    k_zero_pre<<<(NN * 32 + NN / 4 + 255) / 256, 256>>>();
    k_hist<<<(NEDGE + 255) / 256, 256>>>(recvs);
    k_scan<<<1, 1024>>>();
    k_fillcsr<<<(NEDGE + 255) / 256, 256>>>(senders, recvs);
    k_node_enc<<<NODE_TILES, 256, SM_BIG>>>(nodes, enW0, enb0, enW1, enb1);
    k_edge_mma<<<ET128, 256, SM_EDGE>>>(edges, eeb0, recvs);
    k_cagg<<<NODE_TILES, 256, SM_MSG>>>();

    for (int p = 0; p < NPASS; p++)
        k_node_upd_mma<<<NT128, 256, SM_MMA>>>(nb0, nb1, lng, lnb, p & 1);

    k_dec<<<NODE_TILES, 256, SM_DEC>>>(dW0, db0, dW1, db1, out, NPASS & 1);
}